// round 6
// baseline (speedup 1.0000x reference)
#include <cuda_runtime.h>
#include <math.h>

#define FULLMASK 0xffffffffu
#define CB 2
#define CH 32
#define CHKV 8
#define CR 4
#define CD 128
#define CDIM 4096
#define CSTART 32768
#define CPREF 28672
#define CNPG 1792
#define CPAGE 16
#define CTOP 256
#define CSCALE 0.08838834764831845f

#define SCHUNKS 56   // scoring chunks per (b,hkv): 32 pages each
#define PCH 32       // prefix chunks per (b,hkv): 32 union entries each
#define SCH 16       // suffix chunks per (b,hkv): 256 keys each (warp=32-key tile)
#define NPART 512    // partial stride per head (slots 0..383 used)
#define NUSED 384    // 256 prefix + 128 suffix
#define PSTR 132     // floats per partial: m, l, pad, pad, acc[128]

// ---------------- scratch (device globals; no allocation allowed) ------------
__device__ __align__(16) float g_q[CB * CH * CD];
__device__ __align__(16) float g_kn[CB * CHKV * CD];
__device__ __align__(16) float g_vn[CB * CHKV * CD];
__device__ __align__(16) float g_sc[CB * CNPG * CHKV * CR];   // [b][page][hkv][r]
__device__ int   g_top[CB * CHKV * CR * CTOP];
__device__ int   g_uni[CB * CHKV * 1024];            // page | mask<<16
__device__ int   g_ucnt[CB * CHKV];
__device__ __align__(16) float g_part[(size_t)CB * CH * NPART * PSTR];
__device__ __align__(16) float g_attn[CB * CDIM];

__device__ __forceinline__ float dot4(float4 a, float4 b) {
    return a.x * b.x + a.y * b.y + a.z * b.z + a.w * b.w;
}

// 4 dots of one 128-dim key row against 4 q vectors (q broadcast from smem)
__device__ __forceinline__ void dots4(const float* __restrict__ kp, const float* __restrict__ sq,
                                      float& s0, float& s1, float& s2, float& s3) {
    float a0 = 0.f, a1 = 0.f, a2 = 0.f, a3 = 0.f;
#pragma unroll
    for (int d = 0; d < CD; d += 4) {
        float4 k4 = *(const float4*)(kp + d);
        float4 qa = *(const float4*)(sq + d);
        float4 qb = *(const float4*)(sq + CD + d);
        float4 qc = *(const float4*)(sq + 2 * CD + d);
        float4 qd = *(const float4*)(sq + 3 * CD + d);
        a0 += dot4(k4, qa);
        a1 += dot4(k4, qb);
        a2 += dot4(k4, qc);
        a3 += dot4(k4, qd);
    }
    s0 = a0; s1 = a1; s2 = a2; s3 = a3;
}

// one r-component of the 32-key tile flash update; returns this lane's e
__device__ __forceinline__ float tile_flash_r(float s, float& m, float& l, float4& a) {
    float tmax = s;
#pragma unroll
    for (int o = 16; o; o >>= 1) tmax = fmaxf(tmax, __shfl_xor_sync(FULLMASK, tmax, o));
    float nm = fmaxf(m, tmax);
    float cr = __expf(m - nm);
    float e = (s > -1e29f) ? __expf(s - nm) : 0.f;
    float se = e;
#pragma unroll
    for (int o = 16; o; o >>= 1) se += __shfl_xor_sync(FULLMASK, se, o);
    l = l * cr + se;
    m = nm;
    a.x *= cr; a.y *= cr; a.z *= cr; a.w *= cr;
    return e;
}

__device__ __forceinline__ void wpart(float m, float l, float4 a, int b, int hr, int slot, int lane) {
    float* P = g_part + (((size_t)(b * CH + hr)) * NPART + slot) * PSTR;
    if (lane == 0) { P[0] = m; P[1] = l; }
    *(float4*)(P + 4 + lane * 4) = a;
}

// ---------------- 1) QKV GEMV (both batches share each weight row) -----------
__global__ void qkv_kernel(const float* __restrict__ x, const float* __restrict__ wq,
                           const float* __restrict__ wk, const float* __restrict__ wv) {
    __shared__ float sx0[CDIM], sx1[CDIM];
    for (int i = threadIdx.x; i < CDIM; i += 256) { sx0[i] = x[i]; sx1[i] = x[CDIM + i]; }
    __syncthreads();
    int warp = threadIdx.x >> 5, lane = threadIdx.x & 31;
    int row0 = (blockIdx.x * 8 + warp) * 2;
    for (int rr = 0; rr < 2; rr++) {
        int row = row0 + rr;           // 0..6143: [wq 4096 | wk 1024 | wv 1024]
        const float* w;
        if (row < 4096)      w = wq + (size_t)row * CDIM;
        else if (row < 5120) w = wk + (size_t)(row - 4096) * CDIM;
        else                 w = wv + (size_t)(row - 5120) * CDIM;
        float a0 = 0.f, a1 = 0.f;
        for (int j = lane * 4; j < CDIM; j += 128) {
            float4 wv4 = *(const float4*)(w + j);
            float4 x0 = *(const float4*)(sx0 + j);
            float4 x1 = *(const float4*)(sx1 + j);
            a0 += dot4(wv4, x0);
            a1 += dot4(wv4, x1);
        }
        for (int o = 16; o; o >>= 1) {
            a0 += __shfl_xor_sync(FULLMASK, a0, o);
            a1 += __shfl_xor_sync(FULLMASK, a1, o);
        }
        if (lane == 0) {
            if (row < 4096)      { g_q[row] = a0;  g_q[CDIM + row] = a1; }
            else if (row < 5120) { int i = row - 4096; g_kn[i] = a0; g_kn[CHKV * CD + i] = a1; }
            else                 { int i = row - 5120; g_vn[i] = a0; g_vn[CHKV * CD + i] = a1; }
        }
    }
}

// ---------------- 2) RoPE on q and new k (interleaved pairs) -----------------
__global__ void rope_kernel(const float* __restrict__ fc, const float* __restrict__ fs) {
    int idx = blockIdx.x * 256 + threadIdx.x;
    if (idx >= CB * (CH + CHKV) * (CD / 2)) return;
    int i = idx & 63;
    int rem = idx >> 6;               // b*(H+HKV) + hh
    int b = rem / (CH + CHKV);
    int hh = rem % (CH + CHKV);
    float c = fc[i], s = fs[i];
    float* base = (hh < CH) ? (g_q + (b * CH + hh) * CD)
                            : (g_kn + (b * CHKV + (hh - CH)) * CD);
    float t0 = base[2 * i], t1 = base[2 * i + 1];
    base[2 * i]     = t0 * c - t1 * s;
    base[2 * i + 1] = t0 * s + t1 * c;
}

// ---------------- 3) page scoring: key-per-lane, no per-key shfl chains ------
__global__ void score_kernel(const float* __restrict__ ck) {
    __shared__ float sq[CR * CD];
    int bid = blockIdx.x;
    int chunk = bid % SCHUNKS;
    int bh = bid / SCHUNKS;
    int hkv = bh % CHKV, b = bh / CHKV;
    int warp = threadIdx.x >> 5, lane = threadIdx.x & 31;
    for (int i = threadIdx.x; i < CR * CD; i += 256)
        sq[i] = g_q[(b * CH + hkv * CR) * CD + i];
    __syncthreads();
    int page0 = chunk * 32 + warp * 4;
    int kidx = lane & 15;
#pragma unroll
    for (int t = 0; t < 2; t++) {     // 2 tiles x 2 pages (32 keys each)
        int mypage = page0 + t * 2 + (lane >> 4);
        const float* kp = ck + ((size_t)b * CSTART + (size_t)mypage * CPAGE + kidx) * (CHKV * CD) + hkv * CD;
        float s0, s1, s2, s3;
        dots4(kp, sq, s0, s1, s2, s3);
        // page max within each 16-lane group
#pragma unroll
        for (int o = 8; o; o >>= 1) {
            s0 = fmaxf(s0, __shfl_xor_sync(FULLMASK, s0, o));
            s1 = fmaxf(s1, __shfl_xor_sync(FULLMASK, s1, o));
            s2 = fmaxf(s2, __shfl_xor_sync(FULLMASK, s2, o));
            s3 = fmaxf(s3, __shfl_xor_sync(FULLMASK, s3, o));
        }
        if (kidx == 0) {
            float4 res = make_float4(s0, s1, s2, s3);
            *(float4*)(&g_sc[((b * CNPG + mypage) * CHKV + hkv) * CR]) = res;
        }
    }
}

// ---------------- 4) top-256 pages per (b,hkv,r): bitonic, 1024 threads ------
__global__ void topk_kernel() {
    __shared__ unsigned long long sk[2048];
    int inst = blockIdx.x;                    // b*32 + hkv*4 + r
    int r = inst & 3, hkv = (inst >> 2) & 7, b = inst >> 5;
    for (int i = threadIdx.x; i < 2048; i += 1024) {
        unsigned long long key;
        if (i < CNPG) {
            float f = g_sc[((b * CNPG + i) * CHKV + hkv) * CR + r];
            unsigned u = __float_as_uint(f);
            unsigned su = (u >> 31) ? ~u : (u | 0x80000000u);
            unsigned du = ~su;
            key = (((unsigned long long)du) << 32) | (unsigned)i;
        } else {
            key = 0xFFFFFFFFFFFFFFFFull;
        }
        sk[i] = key;
    }
    __syncthreads();
    int t = threadIdx.x;
    for (int k = 2; k <= 2048; k <<= 1) {
        for (int j = k >> 1; j; j >>= 1) {
            int i = ((t & ~(j - 1)) << 1) | (t & (j - 1));
            int ixj = i | j;
            unsigned long long A = sk[i], Bv = sk[ixj];
            bool desc = (i & k) != 0;
            if ((A > Bv) != desc) { sk[i] = Bv; sk[ixj] = A; }
            if (j > 32) __syncthreads();
            else __syncwarp();
        }
        if (k < 2048 && k >= 32) __syncthreads();
    }
    __syncthreads();
    if (t < CTOP)
        g_top[inst * CTOP + t] = (int)(sk[t] & 0xFFFFFFFFu);
}

// ---------------- 5) union of pages across 4 reps + mask, deterministic -----
__global__ void union_kernel() {
    __shared__ int mask[CNPG];
    __shared__ int wtot[8];
    int bh = blockIdx.x;
    int warp = threadIdx.x >> 5, lane = threadIdx.x & 31;
    for (int i = threadIdx.x; i < CNPG; i += 256) mask[i] = 0;
    __syncthreads();
    for (int r = 0; r < CR; r++) {
        int i = threadIdx.x;
        if (i < CTOP) {
            int p = g_top[(bh * CR + r) * CTOP + i];
            atomicOr(&mask[p], 1 << r);
        }
    }
    __syncthreads();
    int base = threadIdx.x * 7;
    int cnt = 0;
    for (int j = 0; j < 7; j++) if (mask[base + j]) cnt++;
    int v = cnt;
    for (int o = 1; o < 32; o <<= 1) {
        int u = __shfl_up_sync(FULLMASK, v, o);
        if (lane >= o) v += u;
    }
    if (lane == 31) wtot[warp] = v;
    __syncthreads();
    if (threadIdx.x == 0) {
        int s = 0;
        for (int i = 0; i < 8; i++) { int t = wtot[i]; wtot[i] = s; s += t; }
        g_ucnt[bh] = (s > 1024) ? 1024 : s;
    }
    __syncthreads();
    int off = v - cnt + wtot[warp];
    for (int j = 0; j < 7; j++) {
        int p = base + j;
        int mk = mask[p];
        if (mk && off < 1024) g_uni[bh * 1024 + off++] = p | (mk << 16);
    }
}

// ---------------- 6) prefix attention: 32-key tiles over union pages ---------
__global__ void prefix_kernel(const float* __restrict__ ck, const float* __restrict__ cv) {
    __shared__ float sq[CR * CD];
    int bid = blockIdx.x;
    int chunk = bid % PCH;
    int bh = bid / PCH;
    int hkv = bh % CHKV, b = bh / CHKV;
    int warp = threadIdx.x >> 5, lane = threadIdx.x & 31;
    for (int i = threadIdx.x; i < CR * CD; i += 256)
        sq[i] = g_q[(b * CH + hkv * CR) * CD + i];
    __syncthreads();
    int cnt = g_ucnt[bh];
    int kidx = lane & 15;
    float m0 = -1e30f, m1 = -1e30f, m2 = -1e30f, m3 = -1e30f;
    float l0 = 0.f, l1 = 0.f, l2 = 0.f, l3 = 0.f;
    float4 A0 = make_float4(0, 0, 0, 0), A1 = A0, A2 = A0, A3 = A0;
#pragma unroll
    for (int t = 0; t < 2; t++) {     // 2 tiles x 2 entries = 4 union entries
        int ei = chunk * 32 + warp * 4 + t * 2 + (lane >> 4);
        int ent = (ei < cnt) ? g_uni[bh * 1024 + ei] : 0;
        int page = ent & 0xFFFF;
        int pm = ent >> 16;
        int pgA = __shfl_sync(FULLMASK, page, 0);
        int pgB = __shfl_sync(FULLMASK, page, 16);
        const float* kp = ck + ((size_t)b * CSTART + (size_t)page * CPAGE + kidx) * (CHKV * CD) + hkv * CD;
        float s0, s1, s2, s3;
        dots4(kp, sq, s0, s1, s2, s3);
        s0 = (pm & 1) ? s0 * CSCALE : -1e30f;
        s1 = (pm & 2) ? s1 * CSCALE : -1e30f;
        s2 = (pm & 4) ? s2 * CSCALE : -1e30f;
        s3 = (pm & 8) ? s3 * CSCALE : -1e30f;
        float e0 = tile_flash_r(s0, m0, l0, A0);
        float e1 = tile_flash_r(s1, m1, l1, A1);
        float e2 = tile_flash_r(s2, m2, l2, A2);
        float e3 = tile_flash_r(s3, m3, l3, A3);
        const float* vA = cv + ((size_t)b * CSTART + (size_t)pgA * CPAGE) * (CHKV * CD) + hkv * CD + lane * 4;
        const float* vB = cv + ((size_t)b * CSTART + (size_t)pgB * CPAGE) * (CHKV * CD) + hkv * CD + lane * 4;
#pragma unroll 4
        for (int k = 0; k < 16; k++) {
            float4 va = *(const float4*)(vA + (size_t)k * (CHKV * CD));
            float4 vb = *(const float4*)(vB + (size_t)k * (CHKV * CD));
            float wa0 = __shfl_sync(FULLMASK, e0, k),      wb0 = __shfl_sync(FULLMASK, e0, k + 16);
            float wa1 = __shfl_sync(FULLMASK, e1, k),      wb1 = __shfl_sync(FULLMASK, e1, k + 16);
            float wa2 = __shfl_sync(FULLMASK, e2, k),      wb2 = __shfl_sync(FULLMASK, e2, k + 16);
            float wa3 = __shfl_sync(FULLMASK, e3, k),      wb3 = __shfl_sync(FULLMASK, e3, k + 16);
            A0.x += wa0 * va.x + wb0 * vb.x; A0.y += wa0 * va.y + wb0 * vb.y;
            A0.z += wa0 * va.z + wb0 * vb.z; A0.w += wa0 * va.w + wb0 * vb.w;
            A1.x += wa1 * va.x + wb1 * vb.x; A1.y += wa1 * va.y + wb1 * vb.y;
            A1.z += wa1 * va.z + wb1 * vb.z; A1.w += wa1 * va.w + wb1 * vb.w;
            A2.x += wa2 * va.x + wb2 * vb.x; A2.y += wa2 * va.y + wb2 * vb.y;
            A2.z += wa2 * va.z + wb2 * vb.z; A2.w += wa2 * va.w + wb2 * vb.w;
            A3.x += wa3 * va.x + wb3 * vb.x; A3.y += wa3 * va.y + wb3 * vb.y;
            A3.z += wa3 * va.z + wb3 * vb.z; A3.w += wa3 * va.w + wb3 * vb.w;
        }
    }
    int slot = chunk * 8 + warp;
    int hr = hkv * CR;
    wpart(m0, l0, A0, b, hr + 0, slot, lane);
    wpart(m1, l1, A1, b, hr + 1, slot, lane);
    wpart(m2, l2, A2, b, hr + 2, slot, lane);
    wpart(m3, l3, A3, b, hr + 3, slot, lane);
}

// ---------------- 7) suffix attention: 32-key tiles over window --------------
__global__ void suffix_kernel(const float* __restrict__ ck, const float* __restrict__ cv) {
    __shared__ float sq[CR * CD];
    int bid = blockIdx.x;
    int chunk = bid % SCH;
    int bh = bid / SCH;
    int hkv = bh % CHKV, b = bh / CHKV;
    int warp = threadIdx.x >> 5, lane = threadIdx.x & 31;
    for (int i = threadIdx.x; i < CR * CD; i += 256)
        sq[i] = g_q[(b * CH + hkv * CR) * CD + i];
    __syncthreads();
    float m0 = -1e30f, m1 = -1e30f, m2 = -1e30f, m3 = -1e30f;
    float l0 = 0.f, l1 = 0.f, l2 = 0.f, l3 = 0.f;
    float4 A0 = make_float4(0, 0, 0, 0), A1 = A0, A2 = A0, A3 = A0;
    size_t pos = (size_t)b * CSTART + CPREF + chunk * 256 + warp * 32;
    const float* kp = ck + (pos + lane) * (CHKV * CD) + hkv * CD;
    float s0, s1, s2, s3;
    dots4(kp, sq, s0, s1, s2, s3);
    s0 *= CSCALE; s1 *= CSCALE; s2 *= CSCALE; s3 *= CSCALE;
    float e0 = tile_flash_r(s0, m0, l0, A0);
    float e1 = tile_flash_r(s1, m1, l1, A1);
    float e2 = tile_flash_r(s2, m2, l2, A2);
    float e3 = tile_flash_r(s3, m3, l3, A3);
    const float* vb = cv + pos * (CHKV * CD) + hkv * CD + lane * 4;
#pragma unroll 8
    for (int k = 0; k < 32; k++) {
        float4 v4 = *(const float4*)(vb + (size_t)k * (CHKV * CD));
        float w0 = __shfl_sync(FULLMASK, e0, k);
        float w1 = __shfl_sync(FULLMASK, e1, k);
        float w2 = __shfl_sync(FULLMASK, e2, k);
        float w3 = __shfl_sync(FULLMASK, e3, k);
        A0.x += w0 * v4.x; A0.y += w0 * v4.y; A0.z += w0 * v4.z; A0.w += w0 * v4.w;
        A1.x += w1 * v4.x; A1.y += w1 * v4.y; A1.z += w1 * v4.z; A1.w += w1 * v4.w;
        A2.x += w2 * v4.x; A2.y += w2 * v4.y; A2.z += w2 * v4.z; A2.w += w2 * v4.w;
        A3.x += w3 * v4.x; A3.y += w3 * v4.y; A3.z += w3 * v4.z; A3.w += w3 * v4.w;
    }
    if (chunk == SCH - 1 && warp == 7) {       // the just-computed token (exact)
        const float* knp = g_kn + (b * CHKV + hkv) * CD + lane * 4;
        const float* vnp = g_vn + (b * CHKV + hkv) * CD + lane * 4;
        float4 kk = *(const float4*)(knp);
        float p0 = dot4(kk, *(const float4*)(sq + 0 * CD + lane * 4));
        float p1 = dot4(kk, *(const float4*)(sq + 1 * CD + lane * 4));
        float p2 = dot4(kk, *(const float4*)(sq + 2 * CD + lane * 4));
        float p3 = dot4(kk, *(const float4*)(sq + 3 * CD + lane * 4));
#pragma unroll
        for (int o = 16; o; o >>= 1) {
            p0 += __shfl_xor_sync(FULLMASK, p0, o);
            p1 += __shfl_xor_sync(FULLMASK, p1, o);
            p2 += __shfl_xor_sync(FULLMASK, p2, o);
            p3 += __shfl_xor_sync(FULLMASK, p3, o);
        }
        p0 *= CSCALE; p1 *= CSCALE; p2 *= CSCALE; p3 *= CSCALE;
        float4 v4 = *(const float4*)(vnp);
        float nm, cr, e;
        nm = fmaxf(m0, p0); cr = __expf(m0 - nm); e = __expf(p0 - nm);
        l0 = l0 * cr + e; m0 = nm;
        A0.x = A0.x * cr + e * v4.x; A0.y = A0.y * cr + e * v4.y;
        A0.z = A0.z * cr + e * v4.z; A0.w = A0.w * cr + e * v4.w;
        nm = fmaxf(m1, p1); cr = __expf(m1 - nm); e = __expf(p1 - nm);
        l1 = l1 * cr + e; m1 = nm;
        A1.x = A1.x * cr + e * v4.x; A1.y = A1.y * cr + e * v4.y;
        A1.z = A1.z * cr + e * v4.z; A1.w = A1.w * cr + e * v4.w;
        nm = fmaxf(m2, p2); cr = __expf(m2 - nm); e = __expf(p2 - nm);
        l2 = l2 * cr + e; m2 = nm;
        A2.x = A2.x * cr + e * v4.x; A2.y = A2.y * cr + e * v4.y;
        A2.z = A2.z * cr + e * v4.z; A2.w = A2.w * cr + e * v4.w;
        nm = fmaxf(m3, p3); cr = __expf(m3 - nm); e = __expf(p3 - nm);
        l3 = l3 * cr + e; m3 = nm;
        A3.x = A3.x * cr + e * v4.x; A3.y = A3.y * cr + e * v4.y;
        A3.z = A3.z * cr + e * v4.z; A3.w = A3.w * cr + e * v4.w;
    }
    int slot = 256 + chunk * 8 + warp;
    int hr = hkv * CR;
    wpart(m0, l0, A0, b, hr + 0, slot, lane);
    wpart(m1, l1, A1, b, hr + 1, slot, lane);
    wpart(m2, l2, A2, b, hr + 2, slot, lane);
    wpart(m3, l3, A3, b, hr + 3, slot, lane);
}

// ---------------- 8) merge all partials (exact logaddexp combine) ------------
__global__ void combine_kernel() {
    int bh = blockIdx.x;                       // b*H + h
    const float* P = g_part + (size_t)bh * NPART * PSTR;
    __shared__ float red[128];
    __shared__ float coef[NUSED];
    int t = threadIdx.x;
    float mloc = -1e30f;
    for (int c = t; c < NUSED; c += 128) mloc = fmaxf(mloc, P[(size_t)c * PSTR]);
    red[t] = mloc;
    for (int o = 64; o; o >>= 1) { __syncthreads(); if (t < o) red[t] = fmaxf(red[t], red[t + o]); }
    __syncthreads();
    float M = red[0];
    __syncthreads();
    float lloc = 0.f;
    for (int c = t; c < NUSED; c += 128) {
        float w = __expf(P[(size_t)c * PSTR] - M);
        coef[c] = w;
        lloc += w * P[(size_t)c * PSTR + 1];
    }
    red[t] = lloc;
    for (int o = 64; o; o >>= 1) { __syncthreads(); if (t < o) red[t] += red[t + o]; }
    __syncthreads();
    float L = red[0];
    float o = 0.f;
    for (int c = 0; c < NUSED; c++) o += coef[c] * P[(size_t)c * PSTR + 4 + t];
    int b = bh >> 5, h = bh & 31;
    g_attn[b * CDIM + h * CD + t] = o / L;
}

// ---------------- 9) output GEMV --------------------------------------------
__global__ void out_kernel(const float* __restrict__ wo, float* __restrict__ out) {
    __shared__ float sa0[CDIM], sa1[CDIM];
    for (int i = threadIdx.x; i < CDIM; i += 256) { sa0[i] = g_attn[i]; sa1[i] = g_attn[CDIM + i]; }
    __syncthreads();
    int warp = threadIdx.x >> 5, lane = threadIdx.x & 31;
    int row0 = (blockIdx.x * 8 + warp) * 4;
    for (int rr = 0; rr < 4; rr++) {
        int row = row0 + rr;
        const float* w = wo + (size_t)row * CDIM;
        float a0 = 0.f, a1 = 0.f;
        for (int j = lane * 4; j < CDIM; j += 128) {
            float4 wv4 = *(const float4*)(w + j);
            float4 x0 = *(const float4*)(sa0 + j);
            float4 x1 = *(const float4*)(sa1 + j);
            a0 += dot4(wv4, x0);
            a1 += dot4(wv4, x1);
        }
        for (int o = 16; o; o >>= 1) {
            a0 += __shfl_xor_sync(FULLMASK, a0, o);
            a1 += __shfl_xor_sync(FULLMASK, a1, o);
        }
        if (lane == 0) { out[row] = a0; out[CDIM + row] = a1; }
    }
}

// ---------------- streams/events for fork-join (created once, host-side) -----
struct SideStream {
    cudaStream_t s2;
    cudaEvent_t e_fork, e_join;
    SideStream() {
        cudaStreamCreateWithFlags(&s2, cudaStreamNonBlocking);
        cudaEventCreateWithFlags(&e_fork, cudaEventDisableTiming);
        cudaEventCreateWithFlags(&e_join, cudaEventDisableTiming);
    }
};
static SideStream g_ss;

// ---------------- launch ------------------------------------------------------
extern "C" void kernel_launch(void* const* d_in, const int* in_sizes, int n_in,
                              void* d_out, int out_size) {
    (void)in_sizes; (void)n_in; (void)out_size;
    const float* x    = (const float*)d_in[0];
    const float* fcos = (const float*)d_in[1];
    const float* fsin = (const float*)d_in[2];
    const float* ck   = (const float*)d_in[3];
    const float* cv   = (const float*)d_in[4];
    const float* wq   = (const float*)d_in[5];
    const float* wk   = (const float*)d_in[6];
    const float* wv   = (const float*)d_in[7];
    const float* wo   = (const float*)d_in[8];
    float* out = (float*)d_out;

    qkv_kernel<<<384, 256>>>(x, wq, wk, wv);
    rope_kernel<<<20, 256>>>(fcos, fsin);

    // fork: suffix depends only on q/kn/vn; run it alongside the scoring chain
    cudaEventRecord(g_ss.e_fork, 0);
    cudaStreamWaitEvent(g_ss.s2, g_ss.e_fork, 0);
    suffix_kernel<<<CB * CHKV * SCH, 256, 0, g_ss.s2>>>(ck, cv);
    cudaEventRecord(g_ss.e_join, g_ss.s2);

    score_kernel<<<CB * CHKV * SCHUNKS, 256>>>(ck);
    topk_kernel<<<CB * CHKV * CR, 1024>>>();
    union_kernel<<<CB * CHKV, 256>>>();
    prefix_kernel<<<CB * CHKV * PCH, 256>>>(ck, cv);

    // join before combine
    cudaStreamWaitEvent(0, g_ss.e_join, 0);
    combine_kernel<<<CB * CH, 128>>>();
    out_kernel<<<128, 256>>>(wo, out);
}

// round 8
// speedup vs baseline: 1.2811x; 1.2811x over previous
#include <cuda_runtime.h>
#include <math.h>

#define FULLMASK 0xffffffffu
#define CB 2
#define CH 32
#define CHKV 8
#define CR 4
#define CD 128
#define CDIM 4096
#define CSTART 32768
#define CPREF 28672
#define CNPG 1792
#define CPAGE 16
#define CTOP 256
#define CSCALE 0.08838834764831845f

#define SCHUNKS 56   // scoring chunks per (b,hkv): 32 pages each
#define PCH 32       // prefix chunks per (b,hkv): 32 union entries each
#define SCH 32       // suffix chunks per (b,hkv): 128 keys each
#define NPART 512    // per head: 256 prefix warp-partials + 256 suffix
#define PSTR 132     // floats per partial: m, l, pad, pad, acc[128]

// ---------------- scratch (device globals; no allocation allowed) ------------
__device__ float g_q[CB * CH * CD];
__device__ float g_kn[CB * CHKV * CD];
__device__ float g_vn[CB * CHKV * CD];
__device__ float g_sc[CB * CNPG * CHKV * CR];        // [b][page][hkv][r]
__device__ int   g_top[CB * CHKV * CR * CTOP];
__device__ int   g_uni[CB * CHKV * 1024];            // page | mask<<16
__device__ int   g_ucnt[CB * CHKV];
__device__ float g_part[(size_t)CB * CH * NPART * PSTR];
__device__ float g_attn[CB * CDIM];

__device__ __forceinline__ float dot4(float4 a, float4 b) {
    return a.x * b.x + a.y * b.y + a.z * b.z + a.w * b.w;
}

// ---------------- 1) QKV GEMV (both batches share each weight row) -----------
__global__ void qkv_kernel(const float* __restrict__ x, const float* __restrict__ wq,
                           const float* __restrict__ wk, const float* __restrict__ wv) {
    __shared__ float sx0[CDIM], sx1[CDIM];
    for (int i = threadIdx.x; i < CDIM; i += 256) { sx0[i] = x[i]; sx1[i] = x[CDIM + i]; }
    __syncthreads();
    int warp = threadIdx.x >> 5, lane = threadIdx.x & 31;
    int row0 = (blockIdx.x * 8 + warp) * 2;
    for (int rr = 0; rr < 2; rr++) {
        int row = row0 + rr;           // 0..6143: [wq 4096 | wk 1024 | wv 1024]
        const float* w;
        if (row < 4096)      w = wq + (size_t)row * CDIM;
        else if (row < 5120) w = wk + (size_t)(row - 4096) * CDIM;
        else                 w = wv + (size_t)(row - 5120) * CDIM;
        float a0 = 0.f, a1 = 0.f;
        for (int j = lane * 4; j < CDIM; j += 128) {
            float4 wv4 = *(const float4*)(w + j);
            float4 x0 = *(const float4*)(sx0 + j);
            float4 x1 = *(const float4*)(sx1 + j);
            a0 += dot4(wv4, x0);
            a1 += dot4(wv4, x1);
        }
        for (int o = 16; o; o >>= 1) {
            a0 += __shfl_xor_sync(FULLMASK, a0, o);
            a1 += __shfl_xor_sync(FULLMASK, a1, o);
        }
        if (lane == 0) {
            if (row < 4096)      { g_q[row] = a0;  g_q[CDIM + row] = a1; }
            else if (row < 5120) { int i = row - 4096; g_kn[i] = a0; g_kn[CHKV * CD + i] = a1; }
            else                 { int i = row - 5120; g_vn[i] = a0; g_vn[CHKV * CD + i] = a1; }
        }
    }
}

// ---------------- 2) RoPE on q and new k (interleaved pairs) -----------------
__global__ void rope_kernel(const float* __restrict__ fc, const float* __restrict__ fs) {
    int idx = blockIdx.x * 256 + threadIdx.x;
    if (idx >= CB * (CH + CHKV) * (CD / 2)) return;
    int i = idx & 63;
    int rem = idx >> 6;               // b*(H+HKV) + hh
    int b = rem / (CH + CHKV);
    int hh = rem % (CH + CHKV);
    float c = fc[i], s = fs[i];
    float* base = (hh < CH) ? (g_q + (b * CH + hh) * CD)
                            : (g_kn + (b * CHKV + (hh - CH)) * CD);
    float t0 = base[2 * i], t1 = base[2 * i + 1];
    base[2 * i]     = t0 * c - t1 * s;
    base[2 * i + 1] = t0 * s + t1 * c;
}

// ---------------- 3) page scoring: half-warp r-pair, 8-key batched -----------
// Half-warp h owns r-pair (2h, 2h+1); lane owns 8 dims. Loads are coalesced
// (16 lanes x 32B contiguous). 8 independent 4-deep shfl chains in flight.
__global__ void score_kernel(const float* __restrict__ ck) {
    int bid = blockIdx.x;
    int chunk = bid % SCHUNKS;
    int bh = bid / SCHUNKS;
    int hkv = bh % CHKV, b = bh / CHKV;
    int warp = threadIdx.x >> 5, lane = threadIdx.x & 31;
    int half = lane >> 4, sub = lane & 15;
    bool p = lane & 1;
    const float* qb = g_q + (b * CH + hkv * CR + 2 * half) * CD + sub * 8;
    float4 q0a = *(const float4*)(qb);
    float4 q0b = *(const float4*)(qb + 4);
    float4 q1a = *(const float4*)(qb + CD);
    float4 q1b = *(const float4*)(qb + CD + 4);
    int page0 = chunk * 32 + warp * 4;
    for (int pp = 0; pp < 4; pp++) {
        int page = page0 + pp;
        const float* kp = ck + (((size_t)b * CSTART + (size_t)page * CPAGE) * CHKV + hkv) * CD + sub * 8;
        float mx = -1e30f;
#pragma unroll
        for (int g = 0; g < 2; g++) {
            float s[8];
#pragma unroll
            for (int k = 0; k < 8; k++) {
                const float* row = kp + (size_t)(g * 8 + k) * (CHKV * CD);
                float4 ka = *(const float4*)(row);
                float4 kb = *(const float4*)(row + 4);
                float v0 = dot4(ka, q0a) + dot4(kb, q0b);
                float v1 = dot4(ka, q1a) + dot4(kb, q1b);
                float a = p ? v1 : v0, bb2 = p ? v0 : v1;
                s[k] = a + __shfl_xor_sync(FULLMASK, bb2, 1);
            }
#pragma unroll
            for (int k = 0; k < 8; k++) {
                float a = s[k];
                a += __shfl_xor_sync(FULLMASK, a, 2);
                a += __shfl_xor_sync(FULLMASK, a, 4);
                a += __shfl_xor_sync(FULLMASK, a, 8);
                s[k] = a;
            }
#pragma unroll
            for (int k = 0; k < 8; k++) mx = fmaxf(mx, s[k]);
        }
        if ((lane & 14) == 0) {        // lanes 0,1,16,17 -> r = 2*half + p
            int r = 2 * half + (int)p;
            g_sc[((b * CNPG + page) * CHKV + hkv) * CR + r] = mx;
        }
    }
}

// ---------------- 4) top-256 pages per (b,hkv,r): bitonic, 1024 threads ------
__global__ void topk_kernel() {
    __shared__ unsigned long long sk[2048];
    int inst = blockIdx.x;                    // b*32 + hkv*4 + r
    int r = inst & 3, hkv = (inst >> 2) & 7, b = inst >> 5;
    for (int i = threadIdx.x; i < 2048; i += 1024) {
        unsigned long long key;
        if (i < CNPG) {
            float f = g_sc[((b * CNPG + i) * CHKV + hkv) * CR + r];
            unsigned u = __float_as_uint(f);
            unsigned su = (u >> 31) ? ~u : (u | 0x80000000u);
            unsigned du = ~su;
            key = (((unsigned long long)du) << 32) | (unsigned)i;
        } else {
            key = 0xFFFFFFFFFFFFFFFFull;
        }
        sk[i] = key;
    }
    __syncthreads();
    int t = threadIdx.x;
    for (int k = 2; k <= 2048; k <<= 1) {
        for (int j = k >> 1; j; j >>= 1) {
            int i = ((t & ~(j - 1)) << 1) | (t & (j - 1));
            int ixj = i | j;
            unsigned long long A = sk[i], Bv = sk[ixj];
            bool desc = (i & k) != 0;
            if ((A > Bv) != desc) { sk[i] = Bv; sk[ixj] = A; }
            if (j > 32) __syncthreads();
            else __syncwarp();
        }
        if (k < 2048 && k >= 32) __syncthreads();
    }
    __syncthreads();
    if (t < CTOP)
        g_top[inst * CTOP + t] = (int)(sk[t] & 0xFFFFFFFFu);
}

// ---------------- 5) union of pages across 4 reps + mask, deterministic -----
__global__ void union_kernel() {
    __shared__ int mask[CNPG];
    __shared__ int wtot[8];
    int bh = blockIdx.x;
    int warp = threadIdx.x >> 5, lane = threadIdx.x & 31;
    for (int i = threadIdx.x; i < CNPG; i += 256) mask[i] = 0;
    __syncthreads();
    for (int r = 0; r < CR; r++) {
        int i = threadIdx.x;
        if (i < CTOP) {
            int p = g_top[(bh * CR + r) * CTOP + i];
            atomicOr(&mask[p], 1 << r);
        }
    }
    __syncthreads();
    int base = threadIdx.x * 7;
    int cnt = 0;
    for (int j = 0; j < 7; j++) if (mask[base + j]) cnt++;
    int v = cnt;
    for (int o = 1; o < 32; o <<= 1) {
        int u = __shfl_up_sync(FULLMASK, v, o);
        if (lane >= o) v += u;
    }
    if (lane == 31) wtot[warp] = v;
    __syncthreads();
    if (threadIdx.x == 0) {
        int s = 0;
        for (int i = 0; i < 8; i++) { int t = wtot[i]; wtot[i] = s; s += t; }
        g_ucnt[bh] = (s > 1024) ? 1024 : s;
    }
    __syncthreads();
    int off = v - cnt + wtot[warp];
    for (int j = 0; j < 7; j++) {
        int p = base + j;
        int mk = mask[p];
        if (mk && off < 1024) g_uni[bh * 1024 + off++] = p | (mk << 16);
    }
}

// ---------------- write one r-state partial (16 lanes of one half) ----------
__device__ __forceinline__ void wpart2(float m, float l, float4 aa, float4 ab,
                                       int b, int hr, int slot, int sub) {
    float* P = g_part + (((size_t)(b * CH + hr)) * NPART + slot) * PSTR;
    if (sub == 0) { P[0] = m; P[1] = l; }
    *(float4*)(P + 4 + sub * 8)     = aa;
    *(float4*)(P + 4 + sub * 8 + 4) = ab;
}

// ---------------- 6) prefix attention: 8-key tile softmax --------------------
__global__ void prefix_kernel(const float* __restrict__ ck, const float* __restrict__ cv) {
    int bid = blockIdx.x;
    int chunk = bid % PCH;
    int bh = bid / PCH;
    int hkv = bh % CHKV, b = bh / CHKV;
    int warp = threadIdx.x >> 5, lane = threadIdx.x & 31;
    int half = lane >> 4, sub = lane & 15;
    bool p = lane & 1;
    int cnt = g_ucnt[bh];
    const float* qb = g_q + (b * CH + hkv * CR + 2 * half) * CD + sub * 8;
    float4 q0a = *(const float4*)(qb);
    float4 q0b = *(const float4*)(qb + 4);
    float4 q1a = *(const float4*)(qb + CD);
    float4 q1b = *(const float4*)(qb + CD + 4);
    float m0 = -1e30f, l0 = 0.f, m1 = -1e30f, l1 = 0.f;
    float4 a0a = make_float4(0, 0, 0, 0), a0b = a0a, a1a = a0a, a1b = a0a;
    int e0i = chunk * 32 + warp * 4;
    for (int ei = e0i; ei < e0i + 4 && ei < cnt; ei++) {
        int ent = g_uni[bh * 1024 + ei];
        int page = ent & 0xFFFF;
        int pm = ent >> 16;
        bool en0 = (pm >> (2 * half)) & 1;
        bool en1 = (pm >> (2 * half + 1)) & 1;
        size_t boff = (((size_t)b * CSTART + (size_t)page * CPAGE) * CHKV + hkv) * CD + sub * 8;
        const float* kp = ck + boff;
        const float* vp = cv + boff;
#pragma unroll
        for (int g = 0; g < 2; g++) {
            float sA[8], sB[8];
#pragma unroll
            for (int k = 0; k < 8; k++) {
                const float* row = kp + (size_t)(g * 8 + k) * (CHKV * CD);
                float4 ka = *(const float4*)(row);
                float4 kb = *(const float4*)(row + 4);
                float v0 = dot4(ka, q0a) + dot4(kb, q0b);
                float v1 = dot4(ka, q1a) + dot4(kb, q1b);
                float a = p ? v1 : v0, bb2 = p ? v0 : v1;
                sA[k] = a + __shfl_xor_sync(FULLMASK, bb2, 1);
            }
#pragma unroll
            for (int k = 0; k < 8; k++) {
                float a = sA[k];
                a += __shfl_xor_sync(FULLMASK, a, 2);
                a += __shfl_xor_sync(FULLMASK, a, 4);
                a += __shfl_xor_sync(FULLMASK, a, 8);
                a *= CSCALE;                     // lane holds s for r=2h+(lane&1)
                float so = __shfl_xor_sync(FULLMASK, a, 1);
                sA[k] = p ? so : a;              // r = 2h (replicated across half)
                sB[k] = p ? a : so;              // r = 2h+1
            }
            float eA[8], eB[8];
            if (en0) {
                float tm = sA[0];
#pragma unroll
                for (int k = 1; k < 8; k++) tm = fmaxf(tm, sA[k]);
                float nm = fmaxf(m0, tm);
                float cr = __expf(m0 - nm);
                float se = 0.f;
#pragma unroll
                for (int k = 0; k < 8; k++) { eA[k] = __expf(sA[k] - nm); se += eA[k]; }
                l0 = l0 * cr + se; m0 = nm;
                a0a.x *= cr; a0a.y *= cr; a0a.z *= cr; a0a.w *= cr;
                a0b.x *= cr; a0b.y *= cr; a0b.z *= cr; a0b.w *= cr;
            }
            if (en1) {
                float tm = sB[0];
#pragma unroll
                for (int k = 1; k < 8; k++) tm = fmaxf(tm, sB[k]);
                float nm = fmaxf(m1, tm);
                float cr = __expf(m1 - nm);
                float se = 0.f;
#pragma unroll
                for (int k = 0; k < 8; k++) { eB[k] = __expf(sB[k] - nm); se += eB[k]; }
                l1 = l1 * cr + se; m1 = nm;
                a1a.x *= cr; a1a.y *= cr; a1a.z *= cr; a1a.w *= cr;
                a1b.x *= cr; a1b.y *= cr; a1b.z *= cr; a1b.w *= cr;
            }
#pragma unroll
            for (int k = 0; k < 8; k++) {
                const float* row = vp + (size_t)(g * 8 + k) * (CHKV * CD);
                float4 va = *(const float4*)(row);
                float4 vb = *(const float4*)(row + 4);
                if (en0) {
                    float e = eA[k];
                    a0a.x += e * va.x; a0a.y += e * va.y; a0a.z += e * va.z; a0a.w += e * va.w;
                    a0b.x += e * vb.x; a0b.y += e * vb.y; a0b.z += e * vb.z; a0b.w += e * vb.w;
                }
                if (en1) {
                    float e = eB[k];
                    a1a.x += e * va.x; a1a.y += e * va.y; a1a.z += e * va.z; a1a.w += e * va.w;
                    a1b.x += e * vb.x; a1b.y += e * vb.y; a1b.z += e * vb.z; a1b.w += e * vb.w;
                }
            }
        }
    }
    int slot = chunk * 8 + warp;
    int hr = hkv * CR + 2 * half;
    wpart2(m0, l0, a0a, a0b, b, hr, slot, sub);
    wpart2(m1, l1, a1a, a1b, b, hr + 1, slot, sub);
}

// ---------------- 7) suffix attention: 8-key tile softmax --------------------
__global__ void suffix_kernel(const float* __restrict__ ck, const float* __restrict__ cv) {
    int bid = blockIdx.x;
    int chunk = bid % SCH;
    int bh = bid / SCH;
    int hkv = bh % CHKV, b = bh / CHKV;
    int warp = threadIdx.x >> 5, lane = threadIdx.x & 31;
    int half = lane >> 4, sub = lane & 15;
    bool p = lane & 1;
    const float* qb = g_q + (b * CH + hkv * CR + 2 * half) * CD + sub * 8;
    float4 q0a = *(const float4*)(qb);
    float4 q0b = *(const float4*)(qb + 4);
    float4 q1a = *(const float4*)(qb + CD);
    float4 q1b = *(const float4*)(qb + CD + 4);
    float m0 = -1e30f, l0 = 0.f, m1 = -1e30f, l1 = 0.f;
    float4 a0a = make_float4(0, 0, 0, 0), a0b = a0a, a1a = a0a, a1b = a0a;
    int key0 = chunk * 128 + warp * 16;
    size_t boff = (((size_t)b * CSTART + CPREF + key0) * CHKV + hkv) * CD + sub * 8;
    const float* kp = ck + boff;
    const float* vp = cv + boff;
#pragma unroll
    for (int g = 0; g < 2; g++) {
        float sA[8], sB[8];
#pragma unroll
        for (int k = 0; k < 8; k++) {
            const float* row = kp + (size_t)(g * 8 + k) * (CHKV * CD);
            float4 ka = *(const float4*)(row);
            float4 kb = *(const float4*)(row + 4);
            float v0 = dot4(ka, q0a) + dot4(kb, q0b);
            float v1 = dot4(ka, q1a) + dot4(kb, q1b);
            float a = p ? v1 : v0, bb2 = p ? v0 : v1;
            sA[k] = a + __shfl_xor_sync(FULLMASK, bb2, 1);
        }
#pragma unroll
        for (int k = 0; k < 8; k++) {
            float a = sA[k];
            a += __shfl_xor_sync(FULLMASK, a, 2);
            a += __shfl_xor_sync(FULLMASK, a, 4);
            a += __shfl_xor_sync(FULLMASK, a, 8);
            a *= CSCALE;
            float so = __shfl_xor_sync(FULLMASK, a, 1);
            sA[k] = p ? so : a;
            sB[k] = p ? a : so;
        }
        float eA[8], eB[8];
        {
            float tm = sA[0];
#pragma unroll
            for (int k = 1; k < 8; k++) tm = fmaxf(tm, sA[k]);
            float nm = fmaxf(m0, tm);
            float cr = __expf(m0 - nm);
            float se = 0.f;
#pragma unroll
            for (int k = 0; k < 8; k++) { eA[k] = __expf(sA[k] - nm); se += eA[k]; }
            l0 = l0 * cr + se; m0 = nm;
            a0a.x *= cr; a0a.y *= cr; a0a.z *= cr; a0a.w *= cr;
            a0b.x *= cr; a0b.y *= cr; a0b.z *= cr; a0b.w *= cr;
        }
        {
            float tm = sB[0];
#pragma unroll
            for (int k = 1; k < 8; k++) tm = fmaxf(tm, sB[k]);
            float nm = fmaxf(m1, tm);
            float cr = __expf(m1 - nm);
            float se = 0.f;
#pragma unroll
            for (int k = 0; k < 8; k++) { eB[k] = __expf(sB[k] - nm); se += eB[k]; }
            l1 = l1 * cr + se; m1 = nm;
            a1a.x *= cr; a1a.y *= cr; a1a.z *= cr; a1a.w *= cr;
            a1b.x *= cr; a1b.y *= cr; a1b.z *= cr; a1b.w *= cr;
        }
#pragma unroll
        for (int k = 0; k < 8; k++) {
            const float* row = vp + (size_t)(g * 8 + k) * (CHKV * CD);
            float4 va = *(const float4*)(row);
            float4 vb = *(const float4*)(row + 4);
            float e = eA[k];
            a0a.x += e * va.x; a0a.y += e * va.y; a0a.z += e * va.z; a0a.w += e * va.w;
            a0b.x += e * vb.x; a0b.y += e * vb.y; a0b.z += e * vb.z; a0b.w += e * vb.w;
            e = eB[k];
            a1a.x += e * va.x; a1a.y += e * va.y; a1a.z += e * va.z; a1a.w += e * va.w;
            a1b.x += e * vb.x; a1b.y += e * vb.y; a1b.z += e * vb.z; a1b.w += e * vb.w;
        }
    }
    if (chunk == SCH - 1 && warp == 7) {       // the just-computed token
        const float* knp = g_kn + (b * CHKV + hkv) * CD + sub * 8;
        const float* vnp = g_vn + (b * CHKV + hkv) * CD + sub * 8;
        float4 ka = *(const float4*)(knp), kb = *(const float4*)(knp + 4);
        float4 va = *(const float4*)(vnp), vb = *(const float4*)(vnp + 4);
        float v0 = dot4(ka, q0a) + dot4(kb, q0b);
        float v1 = dot4(ka, q1a) + dot4(kb, q1b);
        float a = p ? v1 : v0, bb2 = p ? v0 : v1;
        a += __shfl_xor_sync(FULLMASK, bb2, 1);
        a += __shfl_xor_sync(FULLMASK, a, 2);
        a += __shfl_xor_sync(FULLMASK, a, 4);
        a += __shfl_xor_sync(FULLMASK, a, 8);
        a *= CSCALE;
        float so = __shfl_xor_sync(FULLMASK, a, 1);
        float sA = p ? so : a;
        float sB = p ? a : so;
        float nm = fmaxf(m0, sA);
        float cr = __expf(m0 - nm);
        float e = __expf(sA - nm);
        l0 = l0 * cr + e; m0 = nm;
        a0a.x = a0a.x * cr + e * va.x; a0a.y = a0a.y * cr + e * va.y;
        a0a.z = a0a.z * cr + e * va.z; a0a.w = a0a.w * cr + e * va.w;
        a0b.x = a0b.x * cr + e * vb.x; a0b.y = a0b.y * cr + e * vb.y;
        a0b.z = a0b.z * cr + e * vb.z; a0b.w = a0b.w * cr + e * vb.w;
        nm = fmaxf(m1, sB);
        cr = __expf(m1 - nm);
        e = __expf(sB - nm);
        l1 = l1 * cr + e; m1 = nm;
        a1a.x = a1a.x * cr + e * va.x; a1a.y = a1a.y * cr + e * va.y;
        a1a.z = a1a.z * cr + e * va.z; a1a.w = a1a.w * cr + e * va.w;
        a1b.x = a1b.x * cr + e * vb.x; a1b.y = a1b.y * cr + e * vb.y;
        a1b.z = a1b.z * cr + e * vb.z; a1b.w = a1b.w * cr + e * vb.w;
    }
    int slot = 256 + chunk * 8 + warp;
    int hr = hkv * CR + 2 * half;
    wpart2(m0, l0, a0a, a0b, b, hr, slot, sub);
    wpart2(m1, l1, a1a, a1b, b, hr + 1, slot, sub);
}

// ---------------- 8) merge all partials (exact logaddexp combine) ------------
__global__ void combine_kernel() {
    int bh = blockIdx.x;                       // b*H + h
    const float* P = g_part + (size_t)bh * NPART * PSTR;
    __shared__ float red[128];
    __shared__ float coef[NPART];
    int t = threadIdx.x;
    float mloc = -1e30f;
    for (int c = t; c < NPART; c += 128) mloc = fmaxf(mloc, P[(size_t)c * PSTR]);
    red[t] = mloc;
    for (int o = 64; o; o >>= 1) { __syncthreads(); if (t < o) red[t] = fmaxf(red[t], red[t + o]); }
    __syncthreads();
    float M = red[0];
    __syncthreads();
    float lloc = 0.f;
    for (int c = t; c < NPART; c += 128) {
        float w = __expf(P[(size_t)c * PSTR] - M);
        coef[c] = w;
        lloc += w * P[(size_t)c * PSTR + 1];
    }
    red[t] = lloc;
    for (int o = 64; o; o >>= 1) { __syncthreads(); if (t < o) red[t] += red[t + o]; }
    __syncthreads();
    float L = red[0];
    float o = 0.f;
    for (int c = 0; c < NPART; c++) o += coef[c] * P[(size_t)c * PSTR + 4 + t];
    int b = bh >> 5, h = bh & 31;
    g_attn[b * CDIM + h * CD + t] = o / L;
}

// ---------------- 9) output GEMV --------------------------------------------
__global__ void out_kernel(const float* __restrict__ wo, float* __restrict__ out) {
    __shared__ float sa0[CDIM], sa1[CDIM];
    for (int i = threadIdx.x; i < CDIM; i += 256) { sa0[i] = g_attn[i]; sa1[i] = g_attn[CDIM + i]; }
    __syncthreads();
    int warp = threadIdx.x >> 5, lane = threadIdx.x & 31;
    int row0 = (blockIdx.x * 8 + warp) * 4;
    for (int rr = 0; rr < 4; rr++) {
        int row = row0 + rr;
        const float* w = wo + (size_t)row * CDIM;
        float a0 = 0.f, a1 = 0.f;
        for (int j = lane * 4; j < CDIM; j += 128) {
            float4 wv4 = *(const float4*)(w + j);
            float4 x0 = *(const float4*)(sa0 + j);
            float4 x1 = *(const float4*)(sa1 + j);
            a0 += dot4(wv4, x0);
            a1 += dot4(wv4, x1);
        }
        for (int o = 16; o; o >>= 1) {
            a0 += __shfl_xor_sync(FULLMASK, a0, o);
            a1 += __shfl_xor_sync(FULLMASK, a1, o);
        }
        if (lane == 0) { out[row] = a0; out[CDIM + row] = a1; }
    }
}

// ---------------- streams/events for fork-join (created once, host-side) -----
struct SideStream {
    cudaStream_t s2;
    cudaEvent_t e_fork, e_join;
    SideStream() {
        cudaStreamCreateWithFlags(&s2, cudaStreamNonBlocking);
        cudaEventCreateWithFlags(&e_fork, cudaEventDisableTiming);
        cudaEventCreateWithFlags(&e_join, cudaEventDisableTiming);
    }
};
static SideStream g_ss;

// ---------------- launch ------------------------------------------------------
extern "C" void kernel_launch(void* const* d_in, const int* in_sizes, int n_in,
                              void* d_out, int out_size) {
    (void)in_sizes; (void)n_in; (void)out_size;
    const float* x    = (const float*)d_in[0];
    const float* fcos = (const float*)d_in[1];
    const float* fsin = (const float*)d_in[2];
    const float* ck   = (const float*)d_in[3];
    const float* cv   = (const float*)d_in[4];
    const float* wq   = (const float*)d_in[5];
    const float* wk   = (const float*)d_in[6];
    const float* wv   = (const float*)d_in[7];
    const float* wo   = (const float*)d_in[8];
    float* out = (float*)d_out;

    qkv_kernel<<<384, 256>>>(x, wq, wk, wv);
    rope_kernel<<<20, 256>>>(fcos, fsin);

    // fork: suffix depends only on q/kn/vn; run it alongside the scoring chain
    cudaEventRecord(g_ss.e_fork, 0);
    cudaStreamWaitEvent(g_ss.s2, g_ss.e_fork, 0);
    suffix_kernel<<<CB * CHKV * SCH, 256, 0, g_ss.s2>>>(ck, cv);
    cudaEventRecord(g_ss.e_join, g_ss.s2);

    score_kernel<<<CB * CHKV * SCHUNKS, 256>>>(ck);
    topk_kernel<<<CB * CHKV * CR, 1024>>>();
    union_kernel<<<CB * CHKV, 256>>>();
    prefix_kernel<<<CB * CHKV * PCH, 256>>>(ck, cv);

    // join before combine
    cudaStreamWaitEvent(0, g_ss.e_join, 0);
    combine_kernel<<<CB * CH, 128>>>();
    out_kernel<<<128, 256>>>(wo, out);
}

// round 9
// speedup vs baseline: 1.5151x; 1.1827x over previous
#include <cuda_runtime.h>
#include <math.h>

#define FULLMASK 0xffffffffu
#define CB 2
#define CH 32
#define CHKV 8
#define CR 4
#define CD 128
#define CDIM 4096
#define CSTART 32768
#define CPREF 28672
#define CNPG 1792
#define CPAGE 16
#define CTOP 256
#define CSCALE 0.08838834764831845f

#define SCHUNKS 56   // scoring chunks per (b,hkv): 32 pages each
#define PCH 32       // prefix chunks per (b,hkv): 32 union entries each
#define SCH 32       // suffix chunks per (b,hkv): 128 keys each
#define NPART 512    // per head: 256 prefix warp-partials + 256 suffix
#define PSTR 132     // floats per partial: m, l, pad, pad, acc[128]

// ---------------- scratch (device globals; no allocation allowed) ------------
__device__ float g_q[CB * CH * CD];
__device__ float g_kn[CB * CHKV * CD];
__device__ float g_vn[CB * CHKV * CD];
__device__ float g_sc[CB * CNPG * CHKV * CR];        // [b][page][hkv][r]
__device__ __align__(16) float g_dots[(size_t)CB * CHKV * CR * CPREF];  // [bh][r][key]
__device__ int   g_top[CB * CHKV * CR * CTOP];
__device__ int   g_uni[CB * CHKV * 1024];            // page | mask<<16
__device__ int   g_ucnt[CB * CHKV];
__device__ float g_part[(size_t)CB * CH * NPART * PSTR];
__device__ float g_attn[CB * CDIM];

__device__ __forceinline__ float dot4(float4 a, float4 b) {
    return a.x * b.x + a.y * b.y + a.z * b.z + a.w * b.w;
}

// ---------------- 1) QKV GEMV (both batches share each weight row) -----------
__global__ void qkv_kernel(const float* __restrict__ x, const float* __restrict__ wq,
                           const float* __restrict__ wk, const float* __restrict__ wv) {
    __shared__ float sx0[CDIM], sx1[CDIM];
    for (int i = threadIdx.x; i < CDIM; i += 256) { sx0[i] = x[i]; sx1[i] = x[CDIM + i]; }
    __syncthreads();
    int warp = threadIdx.x >> 5, lane = threadIdx.x & 31;
    int row0 = (blockIdx.x * 8 + warp) * 2;
    for (int rr = 0; rr < 2; rr++) {
        int row = row0 + rr;           // 0..6143: [wq 4096 | wk 1024 | wv 1024]
        const float* w;
        if (row < 4096)      w = wq + (size_t)row * CDIM;
        else if (row < 5120) w = wk + (size_t)(row - 4096) * CDIM;
        else                 w = wv + (size_t)(row - 5120) * CDIM;
        float a0 = 0.f, a1 = 0.f;
        for (int j = lane * 4; j < CDIM; j += 128) {
            float4 wv4 = *(const float4*)(w + j);
            float4 x0 = *(const float4*)(sx0 + j);
            float4 x1 = *(const float4*)(sx1 + j);
            a0 += dot4(wv4, x0);
            a1 += dot4(wv4, x1);
        }
        for (int o = 16; o; o >>= 1) {
            a0 += __shfl_xor_sync(FULLMASK, a0, o);
            a1 += __shfl_xor_sync(FULLMASK, a1, o);
        }
        if (lane == 0) {
            if (row < 4096)      { g_q[row] = a0;  g_q[CDIM + row] = a1; }
            else if (row < 5120) { int i = row - 4096; g_kn[i] = a0; g_kn[CHKV * CD + i] = a1; }
            else                 { int i = row - 5120; g_vn[i] = a0; g_vn[CHKV * CD + i] = a1; }
        }
    }
}

// ---------------- 2) RoPE on q and new k (interleaved pairs) -----------------
__global__ void rope_kernel(const float* __restrict__ fc, const float* __restrict__ fs) {
    int idx = blockIdx.x * 256 + threadIdx.x;
    if (idx >= CB * (CH + CHKV) * (CD / 2)) return;
    int i = idx & 63;
    int rem = idx >> 6;               // b*(H+HKV) + hh
    int b = rem / (CH + CHKV);
    int hh = rem % (CH + CHKV);
    float c = fc[i], s = fs[i];
    float* base = (hh < CH) ? (g_q + (b * CH + hh) * CD)
                            : (g_kn + (b * CHKV + (hh - CH)) * CD);
    float t0 = base[2 * i], t1 = base[2 * i + 1];
    base[2 * i]     = t0 * c - t1 * s;
    base[2 * i + 1] = t0 * s + t1 * c;
}

// ---------------- 3) page scoring + dot caching ------------------------------
// Half-warp h owns r-pair (2h, 2h+1); lane owns 8 dims. After the butterfly,
// s[k] (full dot, r = 2h+(lane&1)) is replicated across the 8 lanes sharing
// (h, parity); lanes 0,1,16,17 write per-key dots to g_dots[bh][r][key].
__global__ void score_kernel(const float* __restrict__ ck) {
    int bid = blockIdx.x;
    int chunk = bid % SCHUNKS;
    int bh = bid / SCHUNKS;
    int hkv = bh % CHKV, b = bh / CHKV;
    int warp = threadIdx.x >> 5, lane = threadIdx.x & 31;
    int half = lane >> 4, sub = lane & 15;
    bool p = lane & 1;
    const float* qb = g_q + (b * CH + hkv * CR + 2 * half) * CD + sub * 8;
    float4 q0a = *(const float4*)(qb);
    float4 q0b = *(const float4*)(qb + 4);
    float4 q1a = *(const float4*)(qb + CD);
    float4 q1b = *(const float4*)(qb + CD + 4);
    int page0 = chunk * 32 + warp * 4;
    int r = 2 * half + (int)p;
    float* drow = g_dots + ((size_t)bh * CR + r) * CPREF;
    for (int pp = 0; pp < 4; pp++) {
        int page = page0 + pp;
        const float* kp = ck + (((size_t)b * CSTART + (size_t)page * CPAGE) * CHKV + hkv) * CD + sub * 8;
        float mx = -1e30f;
#pragma unroll
        for (int g = 0; g < 2; g++) {
            float s[8];
#pragma unroll
            for (int k = 0; k < 8; k++) {
                const float* row = kp + (size_t)(g * 8 + k) * (CHKV * CD);
                float4 ka = *(const float4*)(row);
                float4 kb = *(const float4*)(row + 4);
                float v0 = dot4(ka, q0a) + dot4(kb, q0b);
                float v1 = dot4(ka, q1a) + dot4(kb, q1b);
                float a = p ? v1 : v0, bb2 = p ? v0 : v1;
                s[k] = a + __shfl_xor_sync(FULLMASK, bb2, 1);
            }
#pragma unroll
            for (int k = 0; k < 8; k++) {
                float a = s[k];
                a += __shfl_xor_sync(FULLMASK, a, 2);
                a += __shfl_xor_sync(FULLMASK, a, 4);
                a += __shfl_xor_sync(FULLMASK, a, 8);
                s[k] = a;
            }
            if ((lane & 14) == 0) {    // lanes 0,1,16,17
                *(float4*)(drow + page * CPAGE + g * 8)     = make_float4(s[0], s[1], s[2], s[3]);
                *(float4*)(drow + page * CPAGE + g * 8 + 4) = make_float4(s[4], s[5], s[6], s[7]);
            }
#pragma unroll
            for (int k = 0; k < 8; k++) mx = fmaxf(mx, s[k]);
        }
        if ((lane & 14) == 0)
            g_sc[((b * CNPG + page) * CHKV + hkv) * CR + r] = mx;
    }
}

// ---------------- 4) top-256 pages per (b,hkv,r): bitonic, 1024 threads ------
__global__ void topk_kernel() {
    __shared__ unsigned long long sk[2048];
    int inst = blockIdx.x;                    // b*32 + hkv*4 + r
    int r = inst & 3, hkv = (inst >> 2) & 7, b = inst >> 5;
    for (int i = threadIdx.x; i < 2048; i += 1024) {
        unsigned long long key;
        if (i < CNPG) {
            float f = g_sc[((b * CNPG + i) * CHKV + hkv) * CR + r];
            unsigned u = __float_as_uint(f);
            unsigned su = (u >> 31) ? ~u : (u | 0x80000000u);
            unsigned du = ~su;
            key = (((unsigned long long)du) << 32) | (unsigned)i;
        } else {
            key = 0xFFFFFFFFFFFFFFFFull;
        }
        sk[i] = key;
    }
    __syncthreads();
    int t = threadIdx.x;
    for (int k = 2; k <= 2048; k <<= 1) {
        for (int j = k >> 1; j; j >>= 1) {
            int i = ((t & ~(j - 1)) << 1) | (t & (j - 1));
            int ixj = i | j;
            unsigned long long A = sk[i], Bv = sk[ixj];
            bool desc = (i & k) != 0;
            if ((A > Bv) != desc) { sk[i] = Bv; sk[ixj] = A; }
            if (j > 32) __syncthreads();
            else __syncwarp();
        }
        if (k < 2048 && k >= 32) __syncthreads();
    }
    __syncthreads();
    if (t < CTOP)
        g_top[inst * CTOP + t] = (int)(sk[t] & 0xFFFFFFFFu);
}

// ---------------- 5) union of pages across 4 reps + mask, deterministic -----
__global__ void union_kernel() {
    __shared__ int mask[CNPG];
    __shared__ int wtot[8];
    int bh = blockIdx.x;
    int warp = threadIdx.x >> 5, lane = threadIdx.x & 31;
    for (int i = threadIdx.x; i < CNPG; i += 256) mask[i] = 0;
    __syncthreads();
    for (int r = 0; r < CR; r++) {
        int i = threadIdx.x;
        if (i < CTOP) {
            int p = g_top[(bh * CR + r) * CTOP + i];
            atomicOr(&mask[p], 1 << r);
        }
    }
    __syncthreads();
    int base = threadIdx.x * 7;
    int cnt = 0;
    for (int j = 0; j < 7; j++) if (mask[base + j]) cnt++;
    int v = cnt;
    for (int o = 1; o < 32; o <<= 1) {
        int u = __shfl_up_sync(FULLMASK, v, o);
        if (lane >= o) v += u;
    }
    if (lane == 31) wtot[warp] = v;
    __syncthreads();
    if (threadIdx.x == 0) {
        int s = 0;
        for (int i = 0; i < 8; i++) { int t = wtot[i]; wtot[i] = s; s += t; }
        g_ucnt[bh] = (s > 1024) ? 1024 : s;
    }
    __syncthreads();
    int off = v - cnt + wtot[warp];
    for (int j = 0; j < 7; j++) {
        int p = base + j;
        int mk = mask[p];
        if (mk && off < 1024) g_uni[bh * 1024 + off++] = p | (mk << 16);
    }
}

// ---------------- write one r-state partial (16 lanes of one half) ----------
__device__ __forceinline__ void wpart2(float m, float l, float4 aa, float4 ab,
                                       int b, int hr, int slot, int sub) {
    float* P = g_part + (((size_t)(b * CH + hr)) * NPART + slot) * PSTR;
    if (sub == 0) { P[0] = m; P[1] = l; }
    *(float4*)(P + 4 + sub * 8)     = aa;
    *(float4*)(P + 4 + sub * 8 + 4) = ab;
}

// ---------------- 6) prefix attention: dots-fed, V-only, shuffle-free --------
__global__ void prefix_kernel(const float* __restrict__ cv) {
    int bid = blockIdx.x;
    int chunk = bid % PCH;
    int bh = bid / PCH;
    int hkv = bh % CHKV, b = bh / CHKV;
    int warp = threadIdx.x >> 5, lane = threadIdx.x & 31;
    int half = lane >> 4, sub = lane & 15;
    int cnt = g_ucnt[bh];
    float m0 = -1e30f, l0 = 0.f, m1 = -1e30f, l1 = 0.f;
    float4 a0a = make_float4(0, 0, 0, 0), a0b = a0a, a1a = a0a, a1b = a0a;
    const float* dr0 = g_dots + ((size_t)bh * CR + 2 * half) * CPREF;
    const float* dr1 = dr0 + CPREF;
    int e0i = chunk * 32 + warp * 4;
    for (int ei = e0i; ei < e0i + 4 && ei < cnt; ei++) {
        int ent = g_uni[bh * 1024 + ei];
        int page = ent & 0xFFFF;
        int pm = ent >> 16;
        bool en0 = (pm >> (2 * half)) & 1;
        bool en1 = (pm >> (2 * half + 1)) & 1;
        const float* vp = cv + (((size_t)b * CSTART + (size_t)page * CPAGE) * CHKV + hkv) * CD + sub * 8;
#pragma unroll
        for (int g = 0; g < 2; g++) {
            float4 dA0 = *(const float4*)(dr0 + page * CPAGE + g * 8);
            float4 dA1 = *(const float4*)(dr0 + page * CPAGE + g * 8 + 4);
            float4 dB0 = *(const float4*)(dr1 + page * CPAGE + g * 8);
            float4 dB1 = *(const float4*)(dr1 + page * CPAGE + g * 8 + 4);
            float sA[8] = { dA0.x, dA0.y, dA0.z, dA0.w, dA1.x, dA1.y, dA1.z, dA1.w };
            float sB[8] = { dB0.x, dB0.y, dB0.z, dB0.w, dB1.x, dB1.y, dB1.z, dB1.w };
            float eA[8], eB[8];
            if (en0) {
                float tm = sA[0];
#pragma unroll
                for (int k = 1; k < 8; k++) tm = fmaxf(tm, sA[k]);
                float nm = fmaxf(m0, tm * CSCALE);
                float cr = __expf(m0 - nm);
                float se = 0.f;
#pragma unroll
                for (int k = 0; k < 8; k++) { eA[k] = __expf(sA[k] * CSCALE - nm); se += eA[k]; }
                l0 = l0 * cr + se; m0 = nm;
                a0a.x *= cr; a0a.y *= cr; a0a.z *= cr; a0a.w *= cr;
                a0b.x *= cr; a0b.y *= cr; a0b.z *= cr; a0b.w *= cr;
            }
            if (en1) {
                float tm = sB[0];
#pragma unroll
                for (int k = 1; k < 8; k++) tm = fmaxf(tm, sB[k]);
                float nm = fmaxf(m1, tm * CSCALE);
                float cr = __expf(m1 - nm);
                float se = 0.f;
#pragma unroll
                for (int k = 0; k < 8; k++) { eB[k] = __expf(sB[k] * CSCALE - nm); se += eB[k]; }
                l1 = l1 * cr + se; m1 = nm;
                a1a.x *= cr; a1a.y *= cr; a1a.z *= cr; a1a.w *= cr;
                a1b.x *= cr; a1b.y *= cr; a1b.z *= cr; a1b.w *= cr;
            }
#pragma unroll
            for (int k = 0; k < 8; k++) {
                const float* row = vp + (size_t)(g * 8 + k) * (CHKV * CD);
                float4 va = *(const float4*)(row);
                float4 vb = *(const float4*)(row + 4);
                if (en0) {
                    float e = eA[k];
                    a0a.x += e * va.x; a0a.y += e * va.y; a0a.z += e * va.z; a0a.w += e * va.w;
                    a0b.x += e * vb.x; a0b.y += e * vb.y; a0b.z += e * vb.z; a0b.w += e * vb.w;
                }
                if (en1) {
                    float e = eB[k];
                    a1a.x += e * va.x; a1a.y += e * va.y; a1a.z += e * va.z; a1a.w += e * va.w;
                    a1b.x += e * vb.x; a1b.y += e * vb.y; a1b.z += e * vb.z; a1b.w += e * vb.w;
                }
            }
        }
    }
    int slot = chunk * 8 + warp;
    int hr = hkv * CR + 2 * half;
    wpart2(m0, l0, a0a, a0b, b, hr, slot, sub);
    wpart2(m1, l1, a1a, a1b, b, hr + 1, slot, sub);
}

// ---------------- suffix helpers (R5 per-key flash, half-warp r-pair) --------
#define UPD2(MM, LL, ACA, ACB, SV)                                                   \
    do {                                                                             \
        if ((SV) > (MM)) {                                                           \
            float cr_ = __expf((MM) - (SV));                                         \
            MM = (SV); LL *= cr_;                                                    \
            ACA.x *= cr_; ACA.y *= cr_; ACA.z *= cr_; ACA.w *= cr_;                  \
            ACB.x *= cr_; ACB.y *= cr_; ACB.z *= cr_; ACB.w *= cr_;                  \
        }                                                                            \
        float e_ = __expf((SV) - (MM));                                              \
        LL += e_;                                                                    \
        ACA.x += e_ * va.x; ACA.y += e_ * va.y; ACA.z += e_ * va.z; ACA.w += e_ * va.w; \
        ACB.x += e_ * vb.x; ACB.y += e_ * vb.y; ACB.z += e_ * vb.z; ACB.w += e_ * vb.w; \
    } while (0)

struct HState {
    float m0, l0, m1, l1;
    float4 a0a, a0b, a1a, a1b;
};

__device__ __forceinline__ void key_step2(HState& st, float4 ka, float4 kb,
                                          float4 va, float4 vb,
                                          float4 q0a, float4 q0b, float4 q1a, float4 q1b,
                                          bool p) {
    float v0 = dot4(ka, q0a) + dot4(kb, q0b);
    float v1 = dot4(ka, q1a) + dot4(kb, q1b);
    float a = p ? v1 : v0, bb = p ? v0 : v1;
    a += __shfl_xor_sync(FULLMASK, bb, 1);
    a += __shfl_xor_sync(FULLMASK, a, 2);
    a += __shfl_xor_sync(FULLMASK, a, 4);
    a += __shfl_xor_sync(FULLMASK, a, 8);
    a *= CSCALE;
    float so = __shfl_xor_sync(FULLMASK, a, 1);
    float sA = p ? so : a;
    float sB = p ? a : so;
    UPD2(st.m0, st.l0, st.a0a, st.a0b, sA);
    UPD2(st.m1, st.l1, st.a1a, st.a1b, sB);
}

// ---------------- 7) suffix attention (window 4096 + new token) --------------
__global__ void suffix_kernel(const float* __restrict__ ck, const float* __restrict__ cv) {
    int bid = blockIdx.x;
    int chunk = bid % SCH;
    int bh = bid / SCH;
    int hkv = bh % CHKV, b = bh / CHKV;
    int warp = threadIdx.x >> 5, lane = threadIdx.x & 31;
    int half = lane >> 4, sub = lane & 15;
    bool p = lane & 1;
    const float* qb = g_q + (b * CH + hkv * CR + 2 * half) * CD + sub * 8;
    float4 q0a = *(const float4*)(qb);
    float4 q0b = *(const float4*)(qb + 4);
    float4 q1a = *(const float4*)(qb + CD);
    float4 q1b = *(const float4*)(qb + CD + 4);
    HState st;
    st.m0 = st.m1 = -1e30f;
    st.l0 = st.l1 = 0.f;
    st.a0a = st.a0b = st.a1a = st.a1b = make_float4(0.f, 0.f, 0.f, 0.f);
    int key0 = chunk * 128 + warp * 16;
    size_t boff = (((size_t)b * CSTART + CPREF + key0) * CHKV + hkv) * CD + sub * 8;
    const float* kp = ck + boff;
    const float* vp = cv + boff;
    for (int g = 0; g < 8; g++) {
        size_t o0 = (size_t)(2 * g) * (CHKV * CD);
        size_t o1 = (size_t)(2 * g + 1) * (CHKV * CD);
        float4 ka0 = *(const float4*)(kp + o0), kb0 = *(const float4*)(kp + o0 + 4);
        float4 va0 = *(const float4*)(vp + o0), vb0 = *(const float4*)(vp + o0 + 4);
        float4 ka1 = *(const float4*)(kp + o1), kb1 = *(const float4*)(kp + o1 + 4);
        float4 va1 = *(const float4*)(vp + o1), vb1 = *(const float4*)(vp + o1 + 4);
        key_step2(st, ka0, kb0, va0, vb0, q0a, q0b, q1a, q1b, p);
        key_step2(st, ka1, kb1, va1, vb1, q0a, q0b, q1a, q1b, p);
    }
    if (chunk == SCH - 1 && warp == 7) {       // the just-computed token
        const float* knp = g_kn + (b * CHKV + hkv) * CD + sub * 8;
        const float* vnp = g_vn + (b * CHKV + hkv) * CD + sub * 8;
        float4 ka = *(const float4*)(knp), kb = *(const float4*)(knp + 4);
        float4 va = *(const float4*)(vnp), vb = *(const float4*)(vnp + 4);
        key_step2(st, ka, kb, va, vb, q0a, q0b, q1a, q1b, p);
    }
    int slot = 256 + chunk * 8 + warp;
    int hr = hkv * CR + 2 * half;
    wpart2(st.m0, st.l0, st.a0a, st.a0b, b, hr, slot, sub);
    wpart2(st.m1, st.l1, st.a1a, st.a1b, b, hr + 1, slot, sub);
}

// ---------------- 8) merge all partials (exact logaddexp combine) ------------
__global__ void combine_kernel() {
    int bh = blockIdx.x;                       // b*H + h
    const float* P = g_part + (size_t)bh * NPART * PSTR;
    __shared__ float red[128];
    __shared__ float coef[NPART];
    int t = threadIdx.x;
    float mloc = -1e30f;
    for (int c = t; c < NPART; c += 128) mloc = fmaxf(mloc, P[(size_t)c * PSTR]);
    red[t] = mloc;
    for (int o = 64; o; o >>= 1) { __syncthreads(); if (t < o) red[t] = fmaxf(red[t], red[t + o]); }
    __syncthreads();
    float M = red[0];
    __syncthreads();
    float lloc = 0.f;
    for (int c = t; c < NPART; c += 128) {
        float w = __expf(P[(size_t)c * PSTR] - M);
        coef[c] = w;
        lloc += w * P[(size_t)c * PSTR + 1];
    }
    red[t] = lloc;
    for (int o = 64; o; o >>= 1) { __syncthreads(); if (t < o) red[t] += red[t + o]; }
    __syncthreads();
    float L = red[0];
    float o = 0.f;
    for (int c = 0; c < NPART; c++) o += coef[c] * P[(size_t)c * PSTR + 4 + t];
    int b = bh >> 5, h = bh & 31;
    g_attn[b * CDIM + h * CD + t] = o / L;
}

// ---------------- 9) output GEMV --------------------------------------------
__global__ void out_kernel(const float* __restrict__ wo, float* __restrict__ out) {
    __shared__ float sa0[CDIM], sa1[CDIM];
    for (int i = threadIdx.x; i < CDIM; i += 256) { sa0[i] = g_attn[i]; sa1[i] = g_attn[CDIM + i]; }
    __syncthreads();
    int warp = threadIdx.x >> 5, lane = threadIdx.x & 31;
    int row0 = (blockIdx.x * 8 + warp) * 4;
    for (int rr = 0; rr < 4; rr++) {
        int row = row0 + rr;
        const float* w = wo + (size_t)row * CDIM;
        float a0 = 0.f, a1 = 0.f;
        for (int j = lane * 4; j < CDIM; j += 128) {
            float4 wv4 = *(const float4*)(w + j);
            float4 x0 = *(const float4*)(sa0 + j);
            float4 x1 = *(const float4*)(sa1 + j);
            a0 += dot4(wv4, x0);
            a1 += dot4(wv4, x1);
        }
        for (int o = 16; o; o >>= 1) {
            a0 += __shfl_xor_sync(FULLMASK, a0, o);
            a1 += __shfl_xor_sync(FULLMASK, a1, o);
        }
        if (lane == 0) { out[row] = a0; out[CDIM + row] = a1; }
    }
}

// ---------------- streams/events for fork-join (created once, host-side) -----
struct SideStream {
    cudaStream_t s2;
    cudaEvent_t e_fork, e_join;
    SideStream() {
        cudaStreamCreateWithFlags(&s2, cudaStreamNonBlocking);
        cudaEventCreateWithFlags(&e_fork, cudaEventDisableTiming);
        cudaEventCreateWithFlags(&e_join, cudaEventDisableTiming);
    }
};
static SideStream g_ss;

// ---------------- launch ------------------------------------------------------
extern "C" void kernel_launch(void* const* d_in, const int* in_sizes, int n_in,
                              void* d_out, int out_size) {
    (void)in_sizes; (void)n_in; (void)out_size;
    const float* x    = (const float*)d_in[0];
    const float* fcos = (const float*)d_in[1];
    const float* fsin = (const float*)d_in[2];
    const float* ck   = (const float*)d_in[3];
    const float* cv   = (const float*)d_in[4];
    const float* wq   = (const float*)d_in[5];
    const float* wk   = (const float*)d_in[6];
    const float* wv   = (const float*)d_in[7];
    const float* wo   = (const float*)d_in[8];
    float* out = (float*)d_out;

    qkv_kernel<<<384, 256>>>(x, wq, wk, wv);
    rope_kernel<<<20, 256>>>(fcos, fsin);

    // fork: suffix depends only on q/kn/vn; run it alongside the scoring chain
    cudaEventRecord(g_ss.e_fork, 0);
    cudaStreamWaitEvent(g_ss.s2, g_ss.e_fork, 0);
    suffix_kernel<<<CB * CHKV * SCH, 256, 0, g_ss.s2>>>(ck, cv);
    cudaEventRecord(g_ss.e_join, g_ss.s2);

    score_kernel<<<CB * CHKV * SCHUNKS, 256>>>(ck);
    topk_kernel<<<CB * CHKV * CR, 1024>>>();
    union_kernel<<<CB * CHKV, 256>>>();
    prefix_kernel<<<CB * CHKV * PCH, 256>>>(cv);

    // join before combine
    cudaStreamWaitEvent(0, g_ss.e_join, 0);
    combine_kernel<<<CB * CH, 128>>>();
    out_kernel<<<128, 256>>>(wo, out);
}

// round 10
// speedup vs baseline: 1.6205x; 1.0696x over previous
#include <cuda_runtime.h>
#include <math.h>

#define FULLMASK 0xffffffffu
#define CB 2
#define CH 32
#define CHKV 8
#define CR 4
#define CD 128
#define CDIM 4096
#define CSTART 32768
#define CPREF 28672
#define CNPG 1792
#define CPAGE 16
#define CTOP 256
#define CSCALE 0.08838834764831845f

#define SCHUNKS 112  // scoring chunks per (b,hkv): 16 pages each (4 warps x 4)
#define PCH 32       // prefix chunks per (b,hkv): 32 union entries each
#define SCH 32       // suffix chunks per (b,hkv): 128 keys each
#define NPART 512    // per head: 256 prefix warp-partials + 256 suffix
#define PSTR 132     // floats per partial: m, l, pad, pad, acc[128]

// ---------------- scratch (device globals; no allocation allowed) ------------
__device__ float g_q[CB * CH * CD];
__device__ float g_kn[CB * CHKV * CD];
__device__ float g_vn[CB * CHKV * CD];
__device__ float g_sc[CB * CNPG * CHKV * CR];        // [b][page][hkv][r]
__device__ __align__(16) float g_dots[(size_t)CB * CHKV * CR * CPREF];  // [bh][r][key]
__device__ int   g_top[CB * CHKV * CR * CTOP];
__device__ int   g_uni[CB * CHKV * 1024];            // page | mask<<16
__device__ int   g_ucnt[CB * CHKV];
__device__ float g_part[(size_t)CB * CH * NPART * PSTR];
__device__ float g_attn[CB * CDIM];

__device__ __forceinline__ float dot4(float4 a, float4 b) {
    return a.x * b.x + a.y * b.y + a.z * b.z + a.w * b.w;
}

// ---------------- 1) QKV GEMV: 2 rows interleaved for 2x load MLP ------------
__global__ void qkv_kernel(const float* __restrict__ x, const float* __restrict__ wq,
                           const float* __restrict__ wk, const float* __restrict__ wv) {
    __shared__ float sx0[CDIM], sx1[CDIM];
    for (int i = threadIdx.x; i < CDIM; i += 256) { sx0[i] = x[i]; sx1[i] = x[CDIM + i]; }
    __syncthreads();
    int warp = threadIdx.x >> 5, lane = threadIdx.x & 31;
    int rowA = (blockIdx.x * 8 + warp) * 2;   // 0..6143: [wq 4096 | wk 1024 | wv 1024]
    int rowB = rowA + 1;
    const float* wA = (rowA < 4096) ? wq + (size_t)rowA * CDIM
                     : (rowA < 5120) ? wk + (size_t)(rowA - 4096) * CDIM
                                     : wv + (size_t)(rowA - 5120) * CDIM;
    const float* wB = (rowB < 4096) ? wq + (size_t)rowB * CDIM
                     : (rowB < 5120) ? wk + (size_t)(rowB - 4096) * CDIM
                                     : wv + (size_t)(rowB - 5120) * CDIM;
    float a0 = 0.f, a1 = 0.f, b0 = 0.f, b1 = 0.f;
#pragma unroll 4
    for (int j = lane * 4; j < CDIM; j += 128) {
        float4 va = *(const float4*)(wA + j);
        float4 vb = *(const float4*)(wB + j);
        float4 x0 = *(const float4*)(sx0 + j);
        float4 x1 = *(const float4*)(sx1 + j);
        a0 += dot4(va, x0); a1 += dot4(va, x1);
        b0 += dot4(vb, x0); b1 += dot4(vb, x1);
    }
#pragma unroll
    for (int o = 16; o; o >>= 1) {
        a0 += __shfl_xor_sync(FULLMASK, a0, o);
        a1 += __shfl_xor_sync(FULLMASK, a1, o);
        b0 += __shfl_xor_sync(FULLMASK, b0, o);
        b1 += __shfl_xor_sync(FULLMASK, b1, o);
    }
    if (lane == 0) {
        int row = rowA;
        if (row < 4096)      { g_q[row] = a0;  g_q[CDIM + row] = a1; }
        else if (row < 5120) { int i = row - 4096; g_kn[i] = a0; g_kn[CHKV * CD + i] = a1; }
        else                 { int i = row - 5120; g_vn[i] = a0; g_vn[CHKV * CD + i] = a1; }
        row = rowB;
        if (row < 4096)      { g_q[row] = b0;  g_q[CDIM + row] = b1; }
        else if (row < 5120) { int i = row - 4096; g_kn[i] = b0; g_kn[CHKV * CD + i] = b1; }
        else                 { int i = row - 5120; g_vn[i] = b0; g_vn[CHKV * CD + i] = b1; }
    }
}

// ---------------- 2) RoPE on q and new k (interleaved pairs) -----------------
__global__ void rope_kernel(const float* __restrict__ fc, const float* __restrict__ fs) {
    int idx = blockIdx.x * 256 + threadIdx.x;
    if (idx >= CB * (CH + CHKV) * (CD / 2)) return;
    int i = idx & 63;
    int rem = idx >> 6;               // b*(H+HKV) + hh
    int b = rem / (CH + CHKV);
    int hh = rem % (CH + CHKV);
    float c = fc[i], s = fs[i];
    float* base = (hh < CH) ? (g_q + (b * CH + hh) * CD)
                            : (g_kn + (b * CHKV + (hh - CH)) * CD);
    float t0 = base[2 * i], t1 = base[2 * i + 1];
    base[2 * i]     = t0 * c - t1 * s;
    base[2 * i + 1] = t0 * s + t1 * c;
}

// ---------------- 3) page scoring + dot caching (occupancy-pushed) -----------
// 128-thread blocks, launch_bounds to lift warps/SM from 32 to 48.
__global__ void __launch_bounds__(128, 12) score_kernel(const float* __restrict__ ck) {
    int bid = blockIdx.x;
    int chunk = bid % SCHUNKS;
    int bh = bid / SCHUNKS;
    int hkv = bh % CHKV, b = bh / CHKV;
    int warp = threadIdx.x >> 5, lane = threadIdx.x & 31;
    int half = lane >> 4, sub = lane & 15;
    bool p = lane & 1;
    const float* qb = g_q + (b * CH + hkv * CR + 2 * half) * CD + sub * 8;
    float4 q0a = *(const float4*)(qb);
    float4 q0b = *(const float4*)(qb + 4);
    float4 q1a = *(const float4*)(qb + CD);
    float4 q1b = *(const float4*)(qb + CD + 4);
    int page0 = chunk * 16 + warp * 4;
    int r = 2 * half + (int)p;
    float* drow = g_dots + ((size_t)bh * CR + r) * CPREF;
    for (int pp = 0; pp < 4; pp++) {
        int page = page0 + pp;
        const float* kp = ck + (((size_t)b * CSTART + (size_t)page * CPAGE) * CHKV + hkv) * CD + sub * 8;
        float mx = -1e30f;
#pragma unroll
        for (int g = 0; g < 2; g++) {
            float s[8];
#pragma unroll
            for (int k = 0; k < 8; k++) {
                const float* row = kp + (size_t)(g * 8 + k) * (CHKV * CD);
                float4 ka = *(const float4*)(row);
                float4 kb = *(const float4*)(row + 4);
                float v0 = dot4(ka, q0a) + dot4(kb, q0b);
                float v1 = dot4(ka, q1a) + dot4(kb, q1b);
                float a = p ? v1 : v0, bb2 = p ? v0 : v1;
                s[k] = a + __shfl_xor_sync(FULLMASK, bb2, 1);
            }
#pragma unroll
            for (int k = 0; k < 8; k++) {
                float a = s[k];
                a += __shfl_xor_sync(FULLMASK, a, 2);
                a += __shfl_xor_sync(FULLMASK, a, 4);
                a += __shfl_xor_sync(FULLMASK, a, 8);
                s[k] = a;
            }
            if ((lane & 14) == 0) {    // lanes 0,1,16,17
                *(float4*)(drow + page * CPAGE + g * 8)     = make_float4(s[0], s[1], s[2], s[3]);
                *(float4*)(drow + page * CPAGE + g * 8 + 4) = make_float4(s[4], s[5], s[6], s[7]);
            }
#pragma unroll
            for (int k = 0; k < 8; k++) mx = fmaxf(mx, s[k]);
        }
        if ((lane & 14) == 0)
            g_sc[((b * CNPG + page) * CHKV + hkv) * CR + r] = mx;
    }
}

// ---------------- 4) top-256 pages per (b,hkv,r): bitonic, 1024 threads ------
__global__ void topk_kernel() {
    __shared__ unsigned long long sk[2048];
    int inst = blockIdx.x;                    // b*32 + hkv*4 + r
    int r = inst & 3, hkv = (inst >> 2) & 7, b = inst >> 5;
    for (int i = threadIdx.x; i < 2048; i += 1024) {
        unsigned long long key;
        if (i < CNPG) {
            float f = g_sc[((b * CNPG + i) * CHKV + hkv) * CR + r];
            unsigned u = __float_as_uint(f);
            unsigned su = (u >> 31) ? ~u : (u | 0x80000000u);
            unsigned du = ~su;
            key = (((unsigned long long)du) << 32) | (unsigned)i;
        } else {
            key = 0xFFFFFFFFFFFFFFFFull;
        }
        sk[i] = key;
    }
    __syncthreads();
    int t = threadIdx.x;
    for (int k = 2; k <= 2048; k <<= 1) {
        for (int j = k >> 1; j; j >>= 1) {
            int i = ((t & ~(j - 1)) << 1) | (t & (j - 1));
            int ixj = i | j;
            unsigned long long A = sk[i], Bv = sk[ixj];
            bool desc = (i & k) != 0;
            if ((A > Bv) != desc) { sk[i] = Bv; sk[ixj] = A; }
            if (j > 32) __syncthreads();
            else __syncwarp();
        }
        if (k < 2048 && k >= 32) __syncthreads();
    }
    __syncthreads();
    if (t < CTOP)
        g_top[inst * CTOP + t] = (int)(sk[t] & 0xFFFFFFFFu);
}

// ---------------- 5) union of pages across 4 reps + mask, deterministic -----
__global__ void union_kernel() {
    __shared__ int mask[CNPG];
    __shared__ int wtot[8];
    int bh = blockIdx.x;
    int warp = threadIdx.x >> 5, lane = threadIdx.x & 31;
    for (int i = threadIdx.x; i < CNPG; i += 256) mask[i] = 0;
    __syncthreads();
    for (int r = 0; r < CR; r++) {
        int i = threadIdx.x;
        if (i < CTOP) {
            int p = g_top[(bh * CR + r) * CTOP + i];
            atomicOr(&mask[p], 1 << r);
        }
    }
    __syncthreads();
    int base = threadIdx.x * 7;
    int cnt = 0;
    for (int j = 0; j < 7; j++) if (mask[base + j]) cnt++;
    int v = cnt;
    for (int o = 1; o < 32; o <<= 1) {
        int u = __shfl_up_sync(FULLMASK, v, o);
        if (lane >= o) v += u;
    }
    if (lane == 31) wtot[warp] = v;
    __syncthreads();
    if (threadIdx.x == 0) {
        int s = 0;
        for (int i = 0; i < 8; i++) { int t = wtot[i]; wtot[i] = s; s += t; }
        g_ucnt[bh] = (s > 1024) ? 1024 : s;
    }
    __syncthreads();
    int off = v - cnt + wtot[warp];
    for (int j = 0; j < 7; j++) {
        int p = base + j;
        int mk = mask[p];
        if (mk && off < 1024) g_uni[bh * 1024 + off++] = p | (mk << 16);
    }
}

// ---------------- write one r-state partial (16 lanes of one half) ----------
__device__ __forceinline__ void wpart2(float m, float l, float4 aa, float4 ab,
                                       int b, int hr, int slot, int sub) {
    float* P = g_part + (((size_t)(b * CH + hr)) * NPART + slot) * PSTR;
    if (sub == 0) { P[0] = m; P[1] = l; }
    *(float4*)(P + 4 + sub * 8)     = aa;
    *(float4*)(P + 4 + sub * 8 + 4) = ab;
}

// ---------------- 6) prefix attention: dots-fed, V-only, shuffle-free --------
__global__ void prefix_kernel(const float* __restrict__ cv) {
    int bid = blockIdx.x;
    int chunk = bid % PCH;
    int bh = bid / PCH;
    int hkv = bh % CHKV, b = bh / CHKV;
    int warp = threadIdx.x >> 5, lane = threadIdx.x & 31;
    int half = lane >> 4, sub = lane & 15;
    int cnt = g_ucnt[bh];
    float m0 = -1e30f, l0 = 0.f, m1 = -1e30f, l1 = 0.f;
    float4 a0a = make_float4(0, 0, 0, 0), a0b = a0a, a1a = a0a, a1b = a0a;
    const float* dr0 = g_dots + ((size_t)bh * CR + 2 * half) * CPREF;
    const float* dr1 = dr0 + CPREF;
    int e0i = chunk * 32 + warp * 4;
    for (int ei = e0i; ei < e0i + 4 && ei < cnt; ei++) {
        int ent = g_uni[bh * 1024 + ei];
        int page = ent & 0xFFFF;
        int pm = ent >> 16;
        bool en0 = (pm >> (2 * half)) & 1;
        bool en1 = (pm >> (2 * half + 1)) & 1;
        const float* vp = cv + (((size_t)b * CSTART + (size_t)page * CPAGE) * CHKV + hkv) * CD + sub * 8;
#pragma unroll
        for (int g = 0; g < 2; g++) {
            float4 dA0 = *(const float4*)(dr0 + page * CPAGE + g * 8);
            float4 dA1 = *(const float4*)(dr0 + page * CPAGE + g * 8 + 4);
            float4 dB0 = *(const float4*)(dr1 + page * CPAGE + g * 8);
            float4 dB1 = *(const float4*)(dr1 + page * CPAGE + g * 8 + 4);
            float sA[8] = { dA0.x, dA0.y, dA0.z, dA0.w, dA1.x, dA1.y, dA1.z, dA1.w };
            float sB[8] = { dB0.x, dB0.y, dB0.z, dB0.w, dB1.x, dB1.y, dB1.z, dB1.w };
            float eA[8], eB[8];
            if (en0) {
                float tm = sA[0];
#pragma unroll
                for (int k = 1; k < 8; k++) tm = fmaxf(tm, sA[k]);
                float nm = fmaxf(m0, tm * CSCALE);
                float cr = __expf(m0 - nm);
                float se = 0.f;
#pragma unroll
                for (int k = 0; k < 8; k++) { eA[k] = __expf(sA[k] * CSCALE - nm); se += eA[k]; }
                l0 = l0 * cr + se; m0 = nm;
                a0a.x *= cr; a0a.y *= cr; a0a.z *= cr; a0a.w *= cr;
                a0b.x *= cr; a0b.y *= cr; a0b.z *= cr; a0b.w *= cr;
            }
            if (en1) {
                float tm = sB[0];
#pragma unroll
                for (int k = 1; k < 8; k++) tm = fmaxf(tm, sB[k]);
                float nm = fmaxf(m1, tm * CSCALE);
                float cr = __expf(m1 - nm);
                float se = 0.f;
#pragma unroll
                for (int k = 0; k < 8; k++) { eB[k] = __expf(sB[k] * CSCALE - nm); se += eB[k]; }
                l1 = l1 * cr + se; m1 = nm;
                a1a.x *= cr; a1a.y *= cr; a1a.z *= cr; a1a.w *= cr;
                a1b.x *= cr; a1b.y *= cr; a1b.z *= cr; a1b.w *= cr;
            }
#pragma unroll
            for (int k = 0; k < 8; k++) {
                const float* row = vp + (size_t)(g * 8 + k) * (CHKV * CD);
                float4 va = *(const float4*)(row);
                float4 vb = *(const float4*)(row + 4);
                if (en0) {
                    float e = eA[k];
                    a0a.x += e * va.x; a0a.y += e * va.y; a0a.z += e * va.z; a0a.w += e * va.w;
                    a0b.x += e * vb.x; a0b.y += e * vb.y; a0b.z += e * vb.z; a0b.w += e * vb.w;
                }
                if (en1) {
                    float e = eB[k];
                    a1a.x += e * va.x; a1a.y += e * va.y; a1a.z += e * va.z; a1a.w += e * va.w;
                    a1b.x += e * vb.x; a1b.y += e * vb.y; a1b.z += e * vb.z; a1b.w += e * vb.w;
                }
            }
        }
    }
    int slot = chunk * 8 + warp;
    int hr = hkv * CR + 2 * half;
    wpart2(m0, l0, a0a, a0b, b, hr, slot, sub);
    wpart2(m1, l1, a1a, a1b, b, hr + 1, slot, sub);
}

// ---------------- suffix helpers (per-key flash, half-warp r-pair) -----------
#define UPD2(MM, LL, ACA, ACB, SV)                                                   \
    do {                                                                             \
        if ((SV) > (MM)) {                                                           \
            float cr_ = __expf((MM) - (SV));                                         \
            MM = (SV); LL *= cr_;                                                    \
            ACA.x *= cr_; ACA.y *= cr_; ACA.z *= cr_; ACA.w *= cr_;                  \
            ACB.x *= cr_; ACB.y *= cr_; ACB.z *= cr_; ACB.w *= cr_;                  \
        }                                                                            \
        float e_ = __expf((SV) - (MM));                                              \
        LL += e_;                                                                    \
        ACA.x += e_ * va.x; ACA.y += e_ * va.y; ACA.z += e_ * va.z; ACA.w += e_ * va.w; \
        ACB.x += e_ * vb.x; ACB.y += e_ * vb.y; ACB.z += e_ * vb.z; ACB.w += e_ * vb.w; \
    } while (0)

struct HState {
    float m0, l0, m1, l1;
    float4 a0a, a0b, a1a, a1b;
};

__device__ __forceinline__ void key_step2(HState& st, float4 ka, float4 kb,
                                          float4 va, float4 vb,
                                          float4 q0a, float4 q0b, float4 q1a, float4 q1b,
                                          bool p) {
    float v0 = dot4(ka, q0a) + dot4(kb, q0b);
    float v1 = dot4(ka, q1a) + dot4(kb, q1b);
    float a = p ? v1 : v0, bb = p ? v0 : v1;
    a += __shfl_xor_sync(FULLMASK, bb, 1);
    a += __shfl_xor_sync(FULLMASK, a, 2);
    a += __shfl_xor_sync(FULLMASK, a, 4);
    a += __shfl_xor_sync(FULLMASK, a, 8);
    a *= CSCALE;
    float so = __shfl_xor_sync(FULLMASK, a, 1);
    float sA = p ? so : a;
    float sB = p ? a : so;
    UPD2(st.m0, st.l0, st.a0a, st.a0b, sA);
    UPD2(st.m1, st.l1, st.a1a, st.a1b, sB);
}

// ---------------- 7) suffix attention (window 4096 + new token) --------------
__global__ void suffix_kernel(const float* __restrict__ ck, const float* __restrict__ cv) {
    int bid = blockIdx.x;
    int chunk = bid % SCH;
    int bh = bid / SCH;
    int hkv = bh % CHKV, b = bh / CHKV;
    int warp = threadIdx.x >> 5, lane = threadIdx.x & 31;
    int half = lane >> 4, sub = lane & 15;
    bool p = lane & 1;
    const float* qb = g_q + (b * CH + hkv * CR + 2 * half) * CD + sub * 8;
    float4 q0a = *(const float4*)(qb);
    float4 q0b = *(const float4*)(qb + 4);
    float4 q1a = *(const float4*)(qb + CD);
    float4 q1b = *(const float4*)(qb + CD + 4);
    HState st;
    st.m0 = st.m1 = -1e30f;
    st.l0 = st.l1 = 0.f;
    st.a0a = st.a0b = st.a1a = st.a1b = make_float4(0.f, 0.f, 0.f, 0.f);
    int key0 = chunk * 128 + warp * 16;
    size_t boff = (((size_t)b * CSTART + CPREF + key0) * CHKV + hkv) * CD + sub * 8;
    const float* kp = ck + boff;
    const float* vp = cv + boff;
    for (int g = 0; g < 8; g++) {
        size_t o0 = (size_t)(2 * g) * (CHKV * CD);
        size_t o1 = (size_t)(2 * g + 1) * (CHKV * CD);
        float4 ka0 = *(const float4*)(kp + o0), kb0 = *(const float4*)(kp + o0 + 4);
        float4 va0 = *(const float4*)(vp + o0), vb0 = *(const float4*)(vp + o0 + 4);
        float4 ka1 = *(const float4*)(kp + o1), kb1 = *(const float4*)(kp + o1 + 4);
        float4 va1 = *(const float4*)(vp + o1), vb1 = *(const float4*)(vp + o1 + 4);
        key_step2(st, ka0, kb0, va0, vb0, q0a, q0b, q1a, q1b, p);
        key_step2(st, ka1, kb1, va1, vb1, q0a, q0b, q1a, q1b, p);
    }
    if (chunk == SCH - 1 && warp == 7) {       // the just-computed token
        const float* knp = g_kn + (b * CHKV + hkv) * CD + sub * 8;
        const float* vnp = g_vn + (b * CHKV + hkv) * CD + sub * 8;
        float4 ka = *(const float4*)(knp), kb = *(const float4*)(knp + 4);
        float4 va = *(const float4*)(vnp), vb = *(const float4*)(vnp + 4);
        key_step2(st, ka, kb, va, vb, q0a, q0b, q1a, q1b, p);
    }
    int slot = 256 + chunk * 8 + warp;
    int hr = hkv * CR + 2 * half;
    wpart2(st.m0, st.l0, st.a0a, st.a0b, b, hr, slot, sub);
    wpart2(st.m1, st.l1, st.a1a, st.a1b, b, hr + 1, slot, sub);
}

// ---------------- 8) merge all partials (exact logaddexp combine) ------------
__global__ void combine_kernel() {
    int bh = blockIdx.x;                       // b*H + h
    const float* P = g_part + (size_t)bh * NPART * PSTR;
    __shared__ float red[128];
    __shared__ float coef[NPART];
    int t = threadIdx.x;
    float mloc = -1e30f;
    for (int c = t; c < NPART; c += 128) mloc = fmaxf(mloc, P[(size_t)c * PSTR]);
    red[t] = mloc;
    for (int o = 64; o; o >>= 1) { __syncthreads(); if (t < o) red[t] = fmaxf(red[t], red[t + o]); }
    __syncthreads();
    float M = red[0];
    __syncthreads();
    float lloc = 0.f;
    for (int c = t; c < NPART; c += 128) {
        float w = __expf(P[(size_t)c * PSTR] - M);
        coef[c] = w;
        lloc += w * P[(size_t)c * PSTR + 1];
    }
    red[t] = lloc;
    for (int o = 64; o; o >>= 1) { __syncthreads(); if (t < o) red[t] += red[t + o]; }
    __syncthreads();
    float L = red[0];
    float o = 0.f;
    for (int c = 0; c < NPART; c++) o += coef[c] * P[(size_t)c * PSTR + 4 + t];
    int b = bh >> 5, h = bh & 31;
    g_attn[b * CDIM + h * CD + t] = o / L;
}

// ---------------- 9) output GEMV: 2 rows interleaved -------------------------
__global__ void out_kernel(const float* __restrict__ wo, float* __restrict__ out) {
    __shared__ float sa0[CDIM], sa1[CDIM];
    for (int i = threadIdx.x; i < CDIM; i += 256) { sa0[i] = g_attn[i]; sa1[i] = g_attn[CDIM + i]; }
    __syncthreads();
    int warp = threadIdx.x >> 5, lane = threadIdx.x & 31;
    int rowA = (blockIdx.x * 8 + warp) * 2;   // 256 blocks cover 4096 rows
    int rowB = rowA + 1;
    const float* wA = wo + (size_t)rowA * CDIM;
    const float* wB = wo + (size_t)rowB * CDIM;
    float a0 = 0.f, a1 = 0.f, b0 = 0.f, b1 = 0.f;
#pragma unroll 4
    for (int j = lane * 4; j < CDIM; j += 128) {
        float4 va = *(const float4*)(wA + j);
        float4 vb = *(const float4*)(wB + j);
        float4 x0 = *(const float4*)(sa0 + j);
        float4 x1 = *(const float4*)(sa1 + j);
        a0 += dot4(va, x0); a1 += dot4(va, x1);
        b0 += dot4(vb, x0); b1 += dot4(vb, x1);
    }
#pragma unroll
    for (int o = 16; o; o >>= 1) {
        a0 += __shfl_xor_sync(FULLMASK, a0, o);
        a1 += __shfl_xor_sync(FULLMASK, a1, o);
        b0 += __shfl_xor_sync(FULLMASK, b0, o);
        b1 += __shfl_xor_sync(FULLMASK, b1, o);
    }
    if (lane == 0) {
        out[rowA] = a0; out[CDIM + rowA] = a1;
        out[rowB] = b0; out[CDIM + rowB] = b1;
    }
}

// ---------------- streams/events for fork-join (created once, host-side) -----
struct SideStream {
    cudaStream_t s2;
    cudaEvent_t e_fork, e_join;
    SideStream() {
        cudaStreamCreateWithFlags(&s2, cudaStreamNonBlocking);
        cudaEventCreateWithFlags(&e_fork, cudaEventDisableTiming);
        cudaEventCreateWithFlags(&e_join, cudaEventDisableTiming);
    }
};
static SideStream g_ss;

// ---------------- launch ------------------------------------------------------
extern "C" void kernel_launch(void* const* d_in, const int* in_sizes, int n_in,
                              void* d_out, int out_size) {
    (void)in_sizes; (void)n_in; (void)out_size;
    const float* x    = (const float*)d_in[0];
    const float* fcos = (const float*)d_in[1];
    const float* fsin = (const float*)d_in[2];
    const float* ck   = (const float*)d_in[3];
    const float* cv   = (const float*)d_in[4];
    const float* wq   = (const float*)d_in[5];
    const float* wk   = (const float*)d_in[6];
    const float* wv   = (const float*)d_in[7];
    const float* wo   = (const float*)d_in[8];
    float* out = (float*)d_out;

    qkv_kernel<<<384, 256>>>(x, wq, wk, wv);
    rope_kernel<<<20, 256>>>(fcos, fsin);

    // fork: suffix depends only on q/kn/vn; run it alongside the scoring chain
    cudaEventRecord(g_ss.e_fork, 0);
    cudaStreamWaitEvent(g_ss.s2, g_ss.e_fork, 0);
    suffix_kernel<<<CB * CHKV * SCH, 256, 0, g_ss.s2>>>(ck, cv);
    cudaEventRecord(g_ss.e_join, g_ss.s2);

    score_kernel<<<CB * CHKV * SCHUNKS, 128>>>(ck);
    topk_kernel<<<CB * CHKV * CR, 1024>>>();
    union_kernel<<<CB * CHKV, 256>>>();
    prefix_kernel<<<CB * CHKV * PCH, 256>>>(cv);

    // join before combine
    cudaStreamWaitEvent(0, g_ss.e_join, 0);
    combine_kernel<<<CB * CH, 128>>>();
    out_kernel<<<256, 256>>>(wo, out);
}